// round 4
// baseline (speedup 1.0000x reference)
#include <cuda_runtime.h>

#define NROWS 2048
#define NN    2048
#define DIN   256
#define H     32
#define DOUT  256
#define TM    16
#define TN    32

// Scratch (no allocations allowed): attention projections + aggregated neighbors
__device__ float g_xa[NROWS * H];
__device__ float g_na[NN * H];
__device__ float g_agg[NROWS * DIN];

// ---------------------------------------------------------------------------
// K1: x_att = tanh(x@W1+b1)@W2+b2 for both x (ax_*) and neibs (an_*).
// 512 CTAs: first 256 handle x rows, last 256 handle neibs rows. 8 rows/CTA.
// ---------------------------------------------------------------------------
__global__ __launch_bounds__(256) void k1_att(
    const float* __restrict__ x, const float* __restrict__ neibs,
    const float* __restrict__ axw1, const float* __restrict__ axb1,
    const float* __restrict__ axw2, const float* __restrict__ axb2,
    const float* __restrict__ anw1, const float* __restrict__ anb1,
    const float* __restrict__ anw2, const float* __restrict__ anb2)
{
    __shared__ float W1s[DIN * H];   // 32 KB
    __shared__ float W2s[H * H];     // 4 KB
    __shared__ float b1s[H], b2s[H];
    __shared__ float xrow[8][DIN];   // 8 KB

    const int tid = threadIdx.x;
    const int cta = blockIdx.x;
    const bool isx = (cta < 256);
    const float* W1 = isx ? axw1 : anw1;
    const float* W2 = isx ? axw2 : anw2;
    const float* B1 = isx ? axb1 : anb1;
    const float* B2 = isx ? axb2 : anb2;
    const float* src = isx ? x : neibs;
    float* dst = isx ? g_xa : g_na;
    const int row0 = (isx ? cta : cta - 256) * 8;

    for (int i = tid; i < DIN * H / 4; i += 256)
        ((float4*)W1s)[i] = ((const float4*)W1)[i];
    for (int i = tid; i < H * H / 4; i += 256)
        ((float4*)W2s)[i] = ((const float4*)W2)[i];
    if (tid < H) { b1s[tid] = B1[tid]; b2s[tid] = B2[tid]; }
    for (int i = tid; i < 8 * DIN / 4; i += 256)
        ((float4*)xrow)[i] = ((const float4*)(src + (size_t)row0 * DIN))[i];
    __syncthreads();

    const int w = tid >> 5, l = tid & 31;
    float h1 = b1s[l];
    const float* xr = xrow[w];
#pragma unroll 8
    for (int k = 0; k < DIN; k += 4) {
        float4 xv = *(const float4*)(xr + k);
        h1 = fmaf(xv.x, W1s[(k + 0) * H + l], h1);
        h1 = fmaf(xv.y, W1s[(k + 1) * H + l], h1);
        h1 = fmaf(xv.z, W1s[(k + 2) * H + l], h1);
        h1 = fmaf(xv.w, W1s[(k + 3) * H + l], h1);
    }
    h1 = tanhf(h1);
    float h2 = b2s[l];
#pragma unroll
    for (int m = 0; m < H; m++) {
        float hm = __shfl_sync(0xffffffffu, h1, m);
        h2 = fmaf(hm, W2s[m * H + l], h2);
    }
    dst[(row0 + w) * H + l] = h2;
}

// ---------------------------------------------------------------------------
// K2: fused masked-softmax attention aggregation.
//   agg[i,:] = sigmoid( (sum_j exp(s_ij * m_ij) * neibs[j,:]) / sum_j exp(s_ij*m_ij) )
// CTA = 16 target rows; loop neighbor chunks of 32. No max subtraction needed
// (|s| bounded, exp safe in fp32 -> single pass, no rescaling).
// 128 CTAs, 256 threads, 4x4 register tiles for the P@neibs accumulation.
// ---------------------------------------------------------------------------
__global__ __launch_bounds__(256) void k2_attn(
    const float* __restrict__ neibs, const float* __restrict__ mask)
{
    __shared__ float xas[TM][H + 1];
    __shared__ float nas[TN][H + 1];
    __shared__ float Ps[TN][TM];       // [jj][r] -> float4 over rows in PV
    __shared__ float ms[TM][TN];       // staged mask tile (coalesced LDG)
    __shared__ float nbs[TN][DIN];     // 32 KB neighbor features
    __shared__ float dpart[256];
    __shared__ float denoms[TM];

    const int tid = threadIdx.x;
    const int row0 = blockIdx.x * TM;

    for (int i = tid; i < TM * H; i += 256) {
        int r = i >> 5, k = i & 31;
        xas[r][k] = g_xa[(row0 + r) * H + k];
    }

    float acc[4][4];
#pragma unroll
    for (int a = 0; a < 4; a++)
#pragma unroll
        for (int b = 0; b < 4; b++) acc[a][b] = 0.f;

    float dloc = 0.f;
    const int rg = tid >> 6;      // 0..3  (row group for PV)
    const int cg = tid & 63;      // 0..63 (col group * 4)
    const int rS = tid & 15;      // s-phase row (fixed per thread)
    const int jS = tid >> 4;      // s-phase jj base (0..15)

    for (int j0 = 0; j0 < NN; j0 += TN) {
        // ---- stage neighbor att, neighbor features, mask tile ----
        for (int i = tid; i < TN * H; i += 256) {
            int jj = i >> 5, k = i & 31;
            nas[jj][k] = g_na[(j0 + jj) * H + k];
        }
        for (int i = tid; i < TN * DIN / 4; i += 256) {
            int jj = i >> 6, c4 = i & 63;
            ((float4*)nbs[jj])[c4] =
                ((const float4*)(neibs + (size_t)(j0 + jj) * DIN))[c4];
        }
        for (int i = tid; i < TM * TN; i += 256) {
            int r = i >> 5, jj = i & 31;
            ms[r][jj] = mask[(size_t)(row0 + r) * NN + j0 + jj];
        }
        __syncthreads();

        // ---- s-phase: 2 score entries per thread, exp, local denominator ----
#pragma unroll
        for (int e = 0; e < 2; e++) {
            int jj = jS + e * 16;
            float s = 0.f;
#pragma unroll
            for (int k = 0; k < H; k++)
                s = fmaf(xas[rS][k], nas[jj][k], s);
            float p = __expf(s * ms[rS][jj]);
            Ps[jj][rS] = p;
            dloc += p;
        }
        __syncthreads();

        // ---- PV: acc[16x256] += P[16x32] @ nbs[32x256] ----
#pragma unroll 8
        for (int jj = 0; jj < TN; jj++) {
            float4 p4 = *(const float4*)&Ps[jj][rg * 4];
            float4 nb = *(const float4*)&nbs[jj][cg * 4];
            acc[0][0] = fmaf(p4.x, nb.x, acc[0][0]);
            acc[0][1] = fmaf(p4.x, nb.y, acc[0][1]);
            acc[0][2] = fmaf(p4.x, nb.z, acc[0][2]);
            acc[0][3] = fmaf(p4.x, nb.w, acc[0][3]);
            acc[1][0] = fmaf(p4.y, nb.x, acc[1][0]);
            acc[1][1] = fmaf(p4.y, nb.y, acc[1][1]);
            acc[1][2] = fmaf(p4.y, nb.z, acc[1][2]);
            acc[1][3] = fmaf(p4.y, nb.w, acc[1][3]);
            acc[2][0] = fmaf(p4.z, nb.x, acc[2][0]);
            acc[2][1] = fmaf(p4.z, nb.y, acc[2][1]);
            acc[2][2] = fmaf(p4.z, nb.z, acc[2][2]);
            acc[2][3] = fmaf(p4.z, nb.w, acc[2][3]);
            acc[3][0] = fmaf(p4.w, nb.x, acc[3][0]);
            acc[3][1] = fmaf(p4.w, nb.y, acc[3][1]);
            acc[3][2] = fmaf(p4.w, nb.z, acc[3][2]);
            acc[3][3] = fmaf(p4.w, nb.w, acc[3][3]);
        }
        __syncthreads();
    }

    // ---- reduce denominators (each thread's rS is fixed) ----
    dpart[tid] = dloc;
    __syncthreads();
    if (tid < TM) {
        float d = 0.f;
#pragma unroll
        for (int g = 0; g < 16; g++) d += dpart[tid + g * 16];
        denoms[tid] = d;
    }
    __syncthreads();

    // ---- epilogue: normalize, sigmoid, store agg ----
#pragma unroll
    for (int a = 0; a < 4; a++) {
        int r = rg * 4 + a;
        float inv = 1.f / denoms[r];
        float4 o;
        o.x = 1.f / (1.f + __expf(-acc[a][0] * inv));
        o.y = 1.f / (1.f + __expf(-acc[a][1] * inv));
        o.z = 1.f / (1.f + __expf(-acc[a][2] * inv));
        o.w = 1.f / (1.f + __expf(-acc[a][3] * inv));
        *(float4*)&g_agg[(size_t)(row0 + r) * DIN + cg * 4] = o;
    }
}

// ---------------------------------------------------------------------------
// K3: out = sigmoid([x, agg] @ fcx_w + fcx_b). 128 CTAs x 16 rows, K=512.
// ---------------------------------------------------------------------------
__global__ __launch_bounds__(256) void k3_fc(
    const float* __restrict__ x, const float* __restrict__ fcw,
    const float* __restrict__ fcb, float* __restrict__ out)
{
    __shared__ float As[32][TM];      // [kk][r]
    __shared__ float Ws[32][DOUT];    // 32 KB
    __shared__ float bs[DOUT];

    const int tid = threadIdx.x;
    const int row0 = blockIdx.x * TM;
    bs[tid] = fcb[tid];

    float acc[4][4];
#pragma unroll
    for (int a = 0; a < 4; a++)
#pragma unroll
        for (int b = 0; b < 4; b++) acc[a][b] = 0.f;

    const int rg = tid >> 6, cg = tid & 63;

    for (int k0 = 0; k0 < 2 * DIN; k0 += 32) {
        for (int i = tid; i < TM * 32; i += 256) {
            int r = i & 15, kk = i >> 4;
            int k = k0 + kk;
            float v = (k < DIN)
                        ? x[(size_t)(row0 + r) * DIN + k]
                        : g_agg[(size_t)(row0 + r) * DIN + (k - DIN)];
            As[kk][r] = v;
        }
        for (int i = tid; i < 32 * DOUT / 4; i += 256)
            ((float4*)Ws)[i] = ((const float4*)(fcw + (size_t)k0 * DOUT))[i];
        __syncthreads();

#pragma unroll 8
        for (int kk = 0; kk < 32; kk++) {
            float4 a4 = *(const float4*)&As[kk][rg * 4];
            float4 w4 = *(const float4*)&Ws[kk][cg * 4];
            acc[0][0] = fmaf(a4.x, w4.x, acc[0][0]);
            acc[0][1] = fmaf(a4.x, w4.y, acc[0][1]);
            acc[0][2] = fmaf(a4.x, w4.z, acc[0][2]);
            acc[0][3] = fmaf(a4.x, w4.w, acc[0][3]);
            acc[1][0] = fmaf(a4.y, w4.x, acc[1][0]);
            acc[1][1] = fmaf(a4.y, w4.y, acc[1][1]);
            acc[1][2] = fmaf(a4.y, w4.z, acc[1][2]);
            acc[1][3] = fmaf(a4.y, w4.w, acc[1][3]);
            acc[2][0] = fmaf(a4.z, w4.x, acc[2][0]);
            acc[2][1] = fmaf(a4.z, w4.y, acc[2][1]);
            acc[2][2] = fmaf(a4.z, w4.z, acc[2][2]);
            acc[2][3] = fmaf(a4.z, w4.w, acc[2][3]);
            acc[3][0] = fmaf(a4.w, w4.x, acc[3][0]);
            acc[3][1] = fmaf(a4.w, w4.y, acc[3][1]);
            acc[3][2] = fmaf(a4.w, w4.z, acc[3][2]);
            acc[3][3] = fmaf(a4.w, w4.w, acc[3][3]);
        }
        __syncthreads();
    }

#pragma unroll
    for (int a = 0; a < 4; a++) {
        int r = row0 + rg * 4 + a;
        float4 o;
        o.x = 1.f / (1.f + __expf(-(acc[a][0] + bs[cg * 4 + 0])));
        o.y = 1.f / (1.f + __expf(-(acc[a][1] + bs[cg * 4 + 1])));
        o.z = 1.f / (1.f + __expf(-(acc[a][2] + bs[cg * 4 + 2])));
        o.w = 1.f / (1.f + __expf(-(acc[a][3] + bs[cg * 4 + 3])));
        *(float4*)&out[(size_t)r * DOUT + cg * 4] = o;
    }
}

// ---------------------------------------------------------------------------
extern "C" void kernel_launch(void* const* d_in, const int* in_sizes, int n_in,
                              void* d_out, int out_size) {
    const float* x     = (const float*)d_in[0];
    const float* neibs = (const float*)d_in[1];
    // d_in[2] edge_emb: dead code in reference, never read
    const float* mask  = (const float*)d_in[3];
    const float* axw1  = (const float*)d_in[4];
    const float* axb1  = (const float*)d_in[5];
    const float* axw2  = (const float*)d_in[6];
    const float* axb2  = (const float*)d_in[7];
    const float* anw1  = (const float*)d_in[8];
    const float* anb1  = (const float*)d_in[9];
    const float* anw2  = (const float*)d_in[10];
    const float* anb2  = (const float*)d_in[11];
    // d_in[12..15] ae_*: dead code
    const float* fcw   = (const float*)d_in[16];
    const float* fcb   = (const float*)d_in[17];
    float* out = (float*)d_out;

    k1_att<<<512, 256>>>(x, neibs, axw1, axb1, axw2, axb2,
                         anw1, anb1, anw2, anb2);
    k2_attn<<<NROWS / TM, 256>>>(neibs, mask);
    k3_fc<<<NROWS / TM, 256>>>(x, fcw, fcb, out);
}

// round 6
// speedup vs baseline: 1.3661x; 1.3661x over previous
#include <cuda_runtime.h>

#define NROWS 2048
#define NN    2048
#define DIN   256
#define H     32
#define DOUT  256
#define TM    16
#define TN    32
#define NHALF (NN / 2)

// Scratch (no allocations allowed)
__device__ float g_xa[NROWS * H];
__device__ float g_na[NN * H];
__device__ float g_pnum[2][NROWS * DIN];   // split-j partial numerators
__device__ float g_pden[2][NROWS];         // split-j partial denominators

// ---------------------------------------------------------------------------
// K1: att = tanh(x@W1+b1)@W2+b2 for x (ax_*) and neibs (an_*).
// 128 CTAs x 512 threads, 32 rows per CTA (weights amortized 4x vs before).
// Each warp computes 2 rows; x rows read directly from global (warp-broadcast,
// L1-served) so static smem stays under 48KB.
// ---------------------------------------------------------------------------
__global__ __launch_bounds__(512) void k1_att(
    const float* __restrict__ x, const float* __restrict__ neibs,
    const float* __restrict__ axw1, const float* __restrict__ axb1,
    const float* __restrict__ axw2, const float* __restrict__ axb2,
    const float* __restrict__ anw1, const float* __restrict__ anb1,
    const float* __restrict__ anw2, const float* __restrict__ anb2)
{
    __shared__ float W1s[DIN * H];   // 32 KB
    __shared__ float W2s[H * H];     // 4 KB
    __shared__ float b1s[H], b2s[H];

    const int tid = threadIdx.x;
    const int cta = blockIdx.x;
    const bool isx = (cta < 64);
    const float* W1 = isx ? axw1 : anw1;
    const float* W2 = isx ? axw2 : anw2;
    const float* B1 = isx ? axb1 : anb1;
    const float* B2 = isx ? axb2 : anb2;
    const float* src = isx ? x : neibs;
    float* dst = isx ? g_xa : g_na;
    const int row0 = (isx ? cta : cta - 64) * 32;

    for (int i = tid; i < DIN * H / 4; i += 512)
        ((float4*)W1s)[i] = ((const float4*)W1)[i];
    if (tid < H * H / 4)
        ((float4*)W2s)[tid] = ((const float4*)W2)[tid];
    if (tid < H) { b1s[tid] = B1[tid]; b2s[tid] = B2[tid]; }
    __syncthreads();

    const int w = tid >> 5, l = tid & 31;
    const float* r0p = src + (size_t)(row0 + 2 * w) * DIN;
    const float* r1p = r0p + DIN;

    float h1a = b1s[l], h1b = b1s[l];
#pragma unroll 8
    for (int k = 0; k < DIN; k += 4) {
        float4 xa = *(const float4*)(r0p + k);
        float4 xb = *(const float4*)(r1p + k);
        float w0 = W1s[(k + 0) * H + l];
        float w1 = W1s[(k + 1) * H + l];
        float w2 = W1s[(k + 2) * H + l];
        float w3 = W1s[(k + 3) * H + l];
        h1a = fmaf(xa.x, w0, h1a); h1b = fmaf(xb.x, w0, h1b);
        h1a = fmaf(xa.y, w1, h1a); h1b = fmaf(xb.y, w1, h1b);
        h1a = fmaf(xa.z, w2, h1a); h1b = fmaf(xb.z, w2, h1b);
        h1a = fmaf(xa.w, w3, h1a); h1b = fmaf(xb.w, w3, h1b);
    }
    h1a = tanhf(h1a);
    h1b = tanhf(h1b);

    float h2a = b2s[l], h2b = b2s[l];
#pragma unroll
    for (int m = 0; m < H; m++) {
        float wv = W2s[m * H + l];
        h2a = fmaf(__shfl_sync(0xffffffffu, h1a, m), wv, h2a);
        h2b = fmaf(__shfl_sync(0xffffffffu, h1b, m), wv, h2b);
    }
    dst[(size_t)(row0 + 2 * w) * H + l] = h2a;
    dst[(size_t)(row0 + 2 * w + 1) * H + l] = h2b;
}

// ---------------------------------------------------------------------------
// K2a: fused masked-softmax attention, split over the neighbor dimension.
// Grid = 256 CTAs (128 row-tiles x 2 j-halves), 128 threads (4 warps).
// Per-thread 4x8 register tile -> 48B shared loads per 32 FMA (1.5 B/FMA,
// under the 128 B/cyc crossbar at 64 lane-FMA/cyc). Partial numerator +
// denominator written to global; k3 fuses the combine + sigmoid.
// ---------------------------------------------------------------------------
__global__ __launch_bounds__(128) void k2_attn(
    const float* __restrict__ neibs, const float* __restrict__ mask)
{
    __shared__ float xas[TM][H + 1];
    __shared__ float nas[TN][H + 1];
    __shared__ float Ps[TM][TN + 1];   // [r][jj], stride 33 -> conflict-free
    __shared__ float ms[TM][TN + 1];
    __shared__ float nbs[TN][DIN];     // 32 KB
    __shared__ float dpart[128];

    const int tid = threadIdx.x;
    const int tile = blockIdx.x >> 1;
    const int half = blockIdx.x & 1;
    const int row0 = tile * TM;
    const int jbase = half * NHALF;

    for (int i = tid; i < TM * H; i += 128) {
        int r = i >> 5, k = i & 31;
        xas[r][k] = g_xa[(size_t)(row0 + r) * H + k];
    }

    float acc[4][8];
#pragma unroll
    for (int a = 0; a < 4; a++)
#pragma unroll
        for (int b = 0; b < 8; b++) acc[a][b] = 0.f;

    float dloc = 0.f;
    const int w = tid >> 5, l = tid & 31;   // PV: rows w*4.., cols 4l / 128+4l
    const int rS = tid >> 3;                 // s-phase row 0..15
    const int jS = (tid & 7) * 4;            // s-phase jj base

    for (int j0 = 0; j0 < NHALF; j0 += TN) {
        const int jg = jbase + j0;
        // ---- stage neighbor att, neighbor features, mask tile ----
        for (int i = tid; i < TN * H; i += 128) {
            int jj = i >> 5, k = i & 31;
            nas[jj][k] = g_na[(size_t)(jg + jj) * H + k];
        }
        for (int i = tid; i < TN * DIN / 4; i += 128) {
            int jj = i >> 6, c4 = i & 63;
            ((float4*)nbs[jj])[c4] =
                ((const float4*)(neibs + (size_t)(jg + jj) * DIN))[c4];
        }
        for (int i = tid; i < TM * TN; i += 128) {
            int r = i >> 5, jj = i & 31;
            ms[r][jj] = mask[(size_t)(row0 + r) * NN + jg + jj];
        }
        __syncthreads();

        // ---- s-phase: 4 scores per thread (same row -> xas loads amortized)
#pragma unroll
        for (int e = 0; e < 4; e++) {
            int jj = jS + e;
            float s = 0.f;
#pragma unroll
            for (int k = 0; k < H; k++)
                s = fmaf(xas[rS][k], nas[jj][k], s);
            float p = __expf(s * ms[rS][jj]);
            Ps[rS][jj] = p;
            dloc += p;
        }
        __syncthreads();

        // ---- PV: acc[16x256] += P[16x32] @ nbs[32x256], 4x8 per thread ----
#pragma unroll 4
        for (int jj = 0; jj < TN; jj++) {
            float p0 = Ps[w * 4 + 0][jj];
            float p1 = Ps[w * 4 + 1][jj];
            float p2 = Ps[w * 4 + 2][jj];
            float p3 = Ps[w * 4 + 3][jj];
            float4 n0 = *(const float4*)&nbs[jj][l * 4];
            float4 n1 = *(const float4*)&nbs[jj][128 + l * 4];
            acc[0][0] = fmaf(p0, n0.x, acc[0][0]);
            acc[0][1] = fmaf(p0, n0.y, acc[0][1]);
            acc[0][2] = fmaf(p0, n0.z, acc[0][2]);
            acc[0][3] = fmaf(p0, n0.w, acc[0][3]);
            acc[0][4] = fmaf(p0, n1.x, acc[0][4]);
            acc[0][5] = fmaf(p0, n1.y, acc[0][5]);
            acc[0][6] = fmaf(p0, n1.z, acc[0][6]);
            acc[0][7] = fmaf(p0, n1.w, acc[0][7]);
            acc[1][0] = fmaf(p1, n0.x, acc[1][0]);
            acc[1][1] = fmaf(p1, n0.y, acc[1][1]);
            acc[1][2] = fmaf(p1, n0.z, acc[1][2]);
            acc[1][3] = fmaf(p1, n0.w, acc[1][3]);
            acc[1][4] = fmaf(p1, n1.x, acc[1][4]);
            acc[1][5] = fmaf(p1, n1.y, acc[1][5]);
            acc[1][6] = fmaf(p1, n1.z, acc[1][6]);
            acc[1][7] = fmaf(p1, n1.w, acc[1][7]);
            acc[2][0] = fmaf(p2, n0.x, acc[2][0]);
            acc[2][1] = fmaf(p2, n0.y, acc[2][1]);
            acc[2][2] = fmaf(p2, n0.z, acc[2][2]);
            acc[2][3] = fmaf(p2, n0.w, acc[2][3]);
            acc[2][4] = fmaf(p2, n1.x, acc[2][4]);
            acc[2][5] = fmaf(p2, n1.y, acc[2][5]);
            acc[2][6] = fmaf(p2, n1.z, acc[2][6]);
            acc[2][7] = fmaf(p2, n1.w, acc[2][7]);
            acc[3][0] = fmaf(p3, n0.x, acc[3][0]);
            acc[3][1] = fmaf(p3, n0.y, acc[3][1]);
            acc[3][2] = fmaf(p3, n0.z, acc[3][2]);
            acc[3][3] = fmaf(p3, n0.w, acc[3][3]);
            acc[3][4] = fmaf(p3, n1.x, acc[3][4]);
            acc[3][5] = fmaf(p3, n1.y, acc[3][5]);
            acc[3][6] = fmaf(p3, n1.z, acc[3][6]);
            acc[3][7] = fmaf(p3, n1.w, acc[3][7]);
        }
        __syncthreads();
    }

    // ---- partial denominator reduce (each thread kept one fixed row) ----
    dpart[tid] = dloc;
    __syncthreads();
    if (tid < TM) {
        float d = 0.f;
#pragma unroll
        for (int g = 0; g < 8; g++) d += dpart[tid * 8 + g];
        g_pden[half][row0 + tid] = d;
    }

    // ---- store partial numerators (coalesced float4) ----
    float* np = &g_pnum[half][0];
#pragma unroll
    for (int a = 0; a < 4; a++) {
        size_t base = (size_t)(row0 + w * 4 + a) * DIN;
        float4 o0 = make_float4(acc[a][0], acc[a][1], acc[a][2], acc[a][3]);
        float4 o1 = make_float4(acc[a][4], acc[a][5], acc[a][6], acc[a][7]);
        *(float4*)&np[base + 4 * l] = o0;
        *(float4*)&np[base + 128 + 4 * l] = o1;
    }
}

// ---------------------------------------------------------------------------
// K3: out = sigmoid([x, agg] @ fcx_w + fcx_b), with agg materialized on the
// fly from the split-j partials (combine + normalize + sigmoid fused into
// the A-tile staging). 128 CTAs x 16 rows, K=512.
// ---------------------------------------------------------------------------
__global__ __launch_bounds__(256) void k3_fc(
    const float* __restrict__ x, const float* __restrict__ fcw,
    const float* __restrict__ fcb, float* __restrict__ out)
{
    __shared__ float As[32][TM];      // [kk][r]
    __shared__ float Ws[32][DOUT];    // 32 KB
    __shared__ float bs[DOUT];
    __shared__ float invden[TM];

    const int tid = threadIdx.x;
    const int row0 = blockIdx.x * TM;
    bs[tid] = fcb[tid];
    if (tid < TM) {
        float d = g_pden[0][row0 + tid] + g_pden[1][row0 + tid];
        invden[tid] = 1.f / d;
    }

    float acc[4][4];
#pragma unroll
    for (int a = 0; a < 4; a++)
#pragma unroll
        for (int b = 0; b < 4; b++) acc[a][b] = 0.f;

    const int rg = tid >> 6, cg = tid & 63;

    for (int k0 = 0; k0 < 2 * DIN; k0 += 32) {
        for (int i = tid; i < TM * 32; i += 256) {
            int r = i & 15, kk = i >> 4;
            int k = k0 + kk;
            float v;
            if (k < DIN) {
                v = x[(size_t)(row0 + r) * DIN + k];
            } else {
                size_t idx = (size_t)(row0 + r) * DIN + (k - DIN);
                float n = g_pnum[0][idx] + g_pnum[1][idx];
                v = 1.f / (1.f + __expf(-n * invden[r]));
            }
            As[kk][r] = v;
        }
        for (int i = tid; i < 32 * DOUT / 4; i += 256)
            ((float4*)Ws)[i] = ((const float4*)(fcw + (size_t)k0 * DOUT))[i];
        __syncthreads();

#pragma unroll 8
        for (int kk = 0; kk < 32; kk++) {
            float4 a4 = *(const float4*)&As[kk][rg * 4];
            float4 w4 = *(const float4*)&Ws[kk][cg * 4];
            acc[0][0] = fmaf(a4.x, w4.x, acc[0][0]);
            acc[0][1] = fmaf(a4.x, w4.y, acc[0][1]);
            acc[0][2] = fmaf(a4.x, w4.z, acc[0][2]);
            acc[0][3] = fmaf(a4.x, w4.w, acc[0][3]);
            acc[1][0] = fmaf(a4.y, w4.x, acc[1][0]);
            acc[1][1] = fmaf(a4.y, w4.y, acc[1][1]);
            acc[1][2] = fmaf(a4.y, w4.z, acc[1][2]);
            acc[1][3] = fmaf(a4.y, w4.w, acc[1][3]);
            acc[2][0] = fmaf(a4.z, w4.x, acc[2][0]);
            acc[2][1] = fmaf(a4.z, w4.y, acc[2][1]);
            acc[2][2] = fmaf(a4.z, w4.z, acc[2][2]);
            acc[2][3] = fmaf(a4.z, w4.w, acc[2][3]);
            acc[3][0] = fmaf(a4.w, w4.x, acc[3][0]);
            acc[3][1] = fmaf(a4.w, w4.y, acc[3][1]);
            acc[3][2] = fmaf(a4.w, w4.z, acc[3][2]);
            acc[3][3] = fmaf(a4.w, w4.w, acc[3][3]);
        }
        __syncthreads();
    }

#pragma unroll
    for (int a = 0; a < 4; a++) {
        int r = row0 + rg * 4 + a;
        float4 o;
        o.x = 1.f / (1.f + __expf(-(acc[a][0] + bs[cg * 4 + 0])));
        o.y = 1.f / (1.f + __expf(-(acc[a][1] + bs[cg * 4 + 1])));
        o.z = 1.f / (1.f + __expf(-(acc[a][2] + bs[cg * 4 + 2])));
        o.w = 1.f / (1.f + __expf(-(acc[a][3] + bs[cg * 4 + 3])));
        *(float4*)&out[(size_t)r * DOUT + cg * 4] = o;
    }
}

// ---------------------------------------------------------------------------
extern "C" void kernel_launch(void* const* d_in, const int* in_sizes, int n_in,
                              void* d_out, int out_size) {
    const float* x     = (const float*)d_in[0];
    const float* neibs = (const float*)d_in[1];
    // d_in[2] edge_emb: dead code in reference, never read
    const float* mask  = (const float*)d_in[3];
    const float* axw1  = (const float*)d_in[4];
    const float* axb1  = (const float*)d_in[5];
    const float* axw2  = (const float*)d_in[6];
    const float* axb2  = (const float*)d_in[7];
    const float* anw1  = (const float*)d_in[8];
    const float* anb1  = (const float*)d_in[9];
    const float* anw2  = (const float*)d_in[10];
    const float* anb2  = (const float*)d_in[11];
    // d_in[12..15] ae_*: dead code
    const float* fcw   = (const float*)d_in[16];
    const float* fcb   = (const float*)d_in[17];
    float* out = (float*)d_out;

    k1_att<<<128, 512>>>(x, neibs, axw1, axb1, axw2, axb2,
                         anw1, anb1, anw2, anb2);
    k2_attn<<<(NROWS / TM) * 2, 128>>>(neibs, mask);
    k3_fc<<<NROWS / TM, 256>>>(x, fcw, fcb, out);
}

// round 8
// speedup vs baseline: 1.6476x; 1.2061x over previous
#include <cuda_runtime.h>

#define NROWS 2048
#define NN    2048
#define DIN   256
#define H     32
#define DOUT  256
#define TM    16      // k3 row tile
#define TM2   32      // k2 row tile
#define TN    32      // k2 neighbor chunk
#define JSPLIT 4
#define JCH   (NN / JSPLIT)   // 512 neighbors per CTA

// Scratch (no allocations allowed)
__device__ float g_xa[NROWS * H];
__device__ float g_na[NN * H];
__device__ float g_pnum[JSPLIT][NROWS * DIN];   // split-j partial numerators
__device__ float g_pden[JSPLIT][NROWS];         // split-j partial denominators

// ---------------------------------------------------------------------------
// K1: att = tanh(x@W1+b1)@W2+b2 for x (ax_*) and neibs (an_*).
// 128 CTAs x 256 threads; 4 rows per warp so each weight LDS feeds 16 FMAs
// (1 B per lane-FMA -> smem crossbar no longer binding).
// ---------------------------------------------------------------------------
__global__ __launch_bounds__(256) void k1_att(
    const float* __restrict__ x, const float* __restrict__ neibs,
    const float* __restrict__ axw1, const float* __restrict__ axb1,
    const float* __restrict__ axw2, const float* __restrict__ axb2,
    const float* __restrict__ anw1, const float* __restrict__ anb1,
    const float* __restrict__ anw2, const float* __restrict__ anb2)
{
    __shared__ float W1s[DIN * H];   // 32 KB
    __shared__ float W2s[H * H];     // 4 KB
    __shared__ float b1s[H], b2s[H];

    const int tid = threadIdx.x;
    const int cta = blockIdx.x;
    const bool isx = (cta < 64);
    const float* W1 = isx ? axw1 : anw1;
    const float* W2 = isx ? axw2 : anw2;
    const float* B1 = isx ? axb1 : anb1;
    const float* B2 = isx ? axb2 : anb2;
    const float* src = isx ? x : neibs;
    float* dst = isx ? g_xa : g_na;
    const int row0 = (isx ? cta : cta - 64) * 32;

    for (int i = tid; i < DIN * H / 4; i += 256)
        ((float4*)W1s)[i] = ((const float4*)W1)[i];
    if (tid < H * H / 4)
        ((float4*)W2s)[tid] = ((const float4*)W2)[tid];
    if (tid < H) { b1s[tid] = B1[tid]; b2s[tid] = B2[tid]; }
    __syncthreads();

    const int w = tid >> 5, l = tid & 31;
    const float* rp[4];
#pragma unroll
    for (int i = 0; i < 4; i++)
        rp[i] = src + (size_t)(row0 + w * 4 + i) * DIN;

    float h1[4];
#pragma unroll
    for (int i = 0; i < 4; i++) h1[i] = b1s[l];

#pragma unroll 4
    for (int k = 0; k < DIN; k += 4) {
        float4 xv0 = *(const float4*)(rp[0] + k);
        float4 xv1 = *(const float4*)(rp[1] + k);
        float4 xv2 = *(const float4*)(rp[2] + k);
        float4 xv3 = *(const float4*)(rp[3] + k);
        float w0 = W1s[(k + 0) * H + l];
        float w1 = W1s[(k + 1) * H + l];
        float w2 = W1s[(k + 2) * H + l];
        float w3 = W1s[(k + 3) * H + l];
        h1[0] = fmaf(xv0.x, w0, h1[0]); h1[0] = fmaf(xv0.y, w1, h1[0]);
        h1[0] = fmaf(xv0.z, w2, h1[0]); h1[0] = fmaf(xv0.w, w3, h1[0]);
        h1[1] = fmaf(xv1.x, w0, h1[1]); h1[1] = fmaf(xv1.y, w1, h1[1]);
        h1[1] = fmaf(xv1.z, w2, h1[1]); h1[1] = fmaf(xv1.w, w3, h1[1]);
        h1[2] = fmaf(xv2.x, w0, h1[2]); h1[2] = fmaf(xv2.y, w1, h1[2]);
        h1[2] = fmaf(xv2.z, w2, h1[2]); h1[2] = fmaf(xv2.w, w3, h1[2]);
        h1[3] = fmaf(xv3.x, w0, h1[3]); h1[3] = fmaf(xv3.y, w1, h1[3]);
        h1[3] = fmaf(xv3.z, w2, h1[3]); h1[3] = fmaf(xv3.w, w3, h1[3]);
    }
#pragma unroll
    for (int i = 0; i < 4; i++) h1[i] = tanhf(h1[i]);

    float h2[4];
#pragma unroll
    for (int i = 0; i < 4; i++) h2[i] = b2s[l];
#pragma unroll
    for (int m = 0; m < H; m++) {
        float wv = W2s[m * H + l];
        h2[0] = fmaf(__shfl_sync(0xffffffffu, h1[0], m), wv, h2[0]);
        h2[1] = fmaf(__shfl_sync(0xffffffffu, h1[1], m), wv, h2[1]);
        h2[2] = fmaf(__shfl_sync(0xffffffffu, h1[2], m), wv, h2[2]);
        h2[3] = fmaf(__shfl_sync(0xffffffffu, h1[3], m), wv, h2[3]);
    }
#pragma unroll
    for (int i = 0; i < 4; i++)
        dst[(size_t)(row0 + w * 4 + i) * H + l] = h2[i];
}

// ---------------------------------------------------------------------------
// K2: fused masked-softmax attention, j-split by 4.
// Grid = 256 CTAs (64 row-tiles x 4 j-quarters), 128 threads (4 warps).
// 8x8 register tiles; rows assigned per-warp so P loads are warp-uniform
// broadcasts -> only nbs float4 loads cost crossbar bytes (0.5 B/lane-FMA).
// s-phase: thread's xa row hoisted to 32 registers; mask LDG'd to registers.
// ---------------------------------------------------------------------------
__global__ __launch_bounds__(128) void k2_attn(
    const float* __restrict__ neibs, const float* __restrict__ mask)
{
    __shared__ float nas[TN][H + 1];      // 4.2 KB
    __shared__ float Ps[TM2][TN + 1];     // 4.2 KB
    __shared__ float nbs[TN][DIN];        // 32 KB
    __shared__ float dpart[128];

    const int tid = threadIdx.x;
    const int tile = blockIdx.x >> 2;
    const int jq   = blockIdx.x & 3;
    const int row0 = tile * TM2;
    const int jbase = jq * JCH;

    // s-phase assignment: row rS (4 threads/row), 8 contiguous jj per thread
    const int rS = tid >> 2;            // 0..31
    const int jS = (tid & 3) * 8;       // 0,8,16,24
    // PV assignment: warp -> 8 rows, lane -> 8 cols (two 4-col groups)
    const int w = tid >> 5, l = tid & 31;

    // hoist this thread's xa row into registers (broadcast via L1)
    float xreg[H];
    {
        const float4* xp = (const float4*)(g_xa + (size_t)(row0 + rS) * H);
#pragma unroll
        for (int q = 0; q < H / 4; q++) {
            float4 v = xp[q];
            xreg[q * 4 + 0] = v.x; xreg[q * 4 + 1] = v.y;
            xreg[q * 4 + 2] = v.z; xreg[q * 4 + 3] = v.w;
        }
    }

    float acc[8][8];
#pragma unroll
    for (int a = 0; a < 8; a++)
#pragma unroll
        for (int b = 0; b < 8; b++) acc[a][b] = 0.f;

    float dloc = 0.f;

    for (int j0 = 0; j0 < JCH; j0 += TN) {
        const int jg = jbase + j0;

        // ---- stage neighbor att + neighbor features ----
        for (int i = tid; i < TN * H; i += 128) {
            int jj = i >> 5, k = i & 31;
            nas[jj][k] = g_na[(size_t)(jg + jj) * H + k];
        }
        for (int i = tid; i < TN * DIN / 4; i += 128) {
            int jj = i >> 6, c4 = i & 63;
            ((float4*)nbs[jj])[c4] =
                ((const float4*)(neibs + (size_t)(jg + jj) * DIN))[c4];
        }

        // mask for this thread's 8 scores straight to registers (coalesced)
        float mr[8];
        {
            const float* mp = mask + (size_t)(row0 + rS) * NN + jg + jS;
            float4 m0 = *(const float4*)(mp);
            float4 m1 = *(const float4*)(mp + 4);
            mr[0] = m0.x; mr[1] = m0.y; mr[2] = m0.z; mr[3] = m0.w;
            mr[4] = m1.x; mr[5] = m1.y; mr[6] = m1.z; mr[7] = m1.w;
        }
        __syncthreads();

        // ---- s-phase: 8 scores, xa from registers, nas broadcast LDS ----
#pragma unroll
        for (int e = 0; e < 8; e++) {
            int jj = jS + e;
            float s = 0.f;
#pragma unroll
            for (int k = 0; k < H; k++)
                s = fmaf(xreg[k], nas[jj][k], s);
            float p = __expf(s * mr[e]);
            Ps[rS][jj] = p;
            dloc += p;
        }
        __syncthreads();

        // ---- PV: acc[32x256] += P[32x32] @ nbs[32x256], 8x8 per thread ----
#pragma unroll 2
        for (int jj = 0; jj < TN; jj++) {
            float pr[8];
#pragma unroll
            for (int u = 0; u < 8; u++)
                pr[u] = Ps[w * 8 + u][jj];          // warp-uniform broadcast
            float4 n0 = *(const float4*)&nbs[jj][l * 4];
            float4 n1 = *(const float4*)&nbs[jj][128 + l * 4];
#pragma unroll
            for (int u = 0; u < 8; u++) {
                acc[u][0] = fmaf(pr[u], n0.x, acc[u][0]);
                acc[u][1] = fmaf(pr[u], n0.y, acc[u][1]);
                acc[u][2] = fmaf(pr[u], n0.z, acc[u][2]);
                acc[u][3] = fmaf(pr[u], n0.w, acc[u][3]);
                acc[u][4] = fmaf(pr[u], n1.x, acc[u][4]);
                acc[u][5] = fmaf(pr[u], n1.y, acc[u][5]);
                acc[u][6] = fmaf(pr[u], n1.z, acc[u][6]);
                acc[u][7] = fmaf(pr[u], n1.w, acc[u][7]);
            }
        }
        __syncthreads();
    }

    // ---- partial denominator (row rS is fixed per thread; 4 threads/row) ----
    dpart[tid] = dloc;
    __syncthreads();
    if (tid < TM2) {
        float d = dpart[tid * 4] + dpart[tid * 4 + 1]
                + dpart[tid * 4 + 2] + dpart[tid * 4 + 3];
        g_pden[jq][row0 + tid] = d;
    }

    // ---- store partial numerators (coalesced float4) ----
    float* np = &g_pnum[jq][0];
#pragma unroll
    for (int u = 0; u < 8; u++) {
        size_t base = (size_t)(row0 + w * 8 + u) * DIN;
        float4 o0 = make_float4(acc[u][0], acc[u][1], acc[u][2], acc[u][3]);
        float4 o1 = make_float4(acc[u][4], acc[u][5], acc[u][6], acc[u][7]);
        *(float4*)&np[base + 4 * l] = o0;
        *(float4*)&np[base + 128 + 4 * l] = o1;
    }
}

// ---------------------------------------------------------------------------
// K3: out = sigmoid([x, agg] @ fcx_w + fcx_b); agg materialized on the fly
// from the 4 split-j partials (combine + normalize + sigmoid fused into
// the A-tile staging). 128 CTAs x 16 rows, K=512.
// ---------------------------------------------------------------------------
__global__ __launch_bounds__(256) void k3_fc(
    const float* __restrict__ x, const float* __restrict__ fcw,
    const float* __restrict__ fcb, float* __restrict__ out)
{
    __shared__ float As[32][TM];      // [kk][r]
    __shared__ float Ws[32][DOUT];    // 32 KB
    __shared__ float bs[DOUT];
    __shared__ float invden[TM];

    const int tid = threadIdx.x;
    const int row0 = blockIdx.x * TM;
    bs[tid] = fcb[tid];
    if (tid < TM) {
        float d = g_pden[0][row0 + tid] + g_pden[1][row0 + tid]
                + g_pden[2][row0 + tid] + g_pden[3][row0 + tid];
        invden[tid] = 1.f / d;
    }

    float acc[4][4];
#pragma unroll
    for (int a = 0; a < 4; a++)
#pragma unroll
        for (int b = 0; b < 4; b++) acc[a][b] = 0.f;

    const int rg = tid >> 6, cg = tid & 63;

    for (int k0 = 0; k0 < 2 * DIN; k0 += 32) {
        for (int i = tid; i < TM * 32; i += 256) {
            int r = i & 15, kk = i >> 4;
            int k = k0 + kk;
            float v;
            if (k < DIN) {
                v = x[(size_t)(row0 + r) * DIN + k];
            } else {
                size_t idx = (size_t)(row0 + r) * DIN + (k - DIN);
                float n = g_pnum[0][idx] + g_pnum[1][idx]
                        + g_pnum[2][idx] + g_pnum[3][idx];
                v = 1.f / (1.f + __expf(-n * invden[r]));
            }
            As[kk][r] = v;
        }
        for (int i = tid; i < 32 * DOUT / 4; i += 256)
            ((float4*)Ws)[i] = ((const float4*)(fcw + (size_t)k0 * DOUT))[i];
        __syncthreads();

#pragma unroll 8
        for (int kk = 0; kk < 32; kk++) {
            float4 a4 = *(const float4*)&As[kk][rg * 4];
            float4 w4 = *(const float4*)&Ws[kk][cg * 4];
            acc[0][0] = fmaf(a4.x, w4.x, acc[0][0]);
            acc[0][1] = fmaf(a4.x, w4.y, acc[0][1]);
            acc[0][2] = fmaf(a4.x, w4.z, acc[0][2]);
            acc[0][3] = fmaf(a4.x, w4.w, acc[0][3]);
            acc[1][0] = fmaf(a4.y, w4.x, acc[1][0]);
            acc[1][1] = fmaf(a4.y, w4.y, acc[1][1]);
            acc[1][2] = fmaf(a4.y, w4.z, acc[1][2]);
            acc[1][3] = fmaf(a4.y, w4.w, acc[1][3]);
            acc[2][0] = fmaf(a4.z, w4.x, acc[2][0]);
            acc[2][1] = fmaf(a4.z, w4.y, acc[2][1]);
            acc[2][2] = fmaf(a4.z, w4.z, acc[2][2]);
            acc[2][3] = fmaf(a4.z, w4.w, acc[2][3]);
            acc[3][0] = fmaf(a4.w, w4.x, acc[3][0]);
            acc[3][1] = fmaf(a4.w, w4.y, acc[3][1]);
            acc[3][2] = fmaf(a4.w, w4.z, acc[3][2]);
            acc[3][3] = fmaf(a4.w, w4.w, acc[3][3]);
        }
        __syncthreads();
    }

#pragma unroll
    for (int a = 0; a < 4; a++) {
        int r = row0 + rg * 4 + a;
        float4 o;
        o.x = 1.f / (1.f + __expf(-(acc[a][0] + bs[cg * 4 + 0])));
        o.y = 1.f / (1.f + __expf(-(acc[a][1] + bs[cg * 4 + 1])));
        o.z = 1.f / (1.f + __expf(-(acc[a][2] + bs[cg * 4 + 2])));
        o.w = 1.f / (1.f + __expf(-(acc[a][3] + bs[cg * 4 + 3])));
        *(float4*)&out[(size_t)r * DOUT + cg * 4] = o;
    }
}

// ---------------------------------------------------------------------------
extern "C" void kernel_launch(void* const* d_in, const int* in_sizes, int n_in,
                              void* d_out, int out_size) {
    const float* x     = (const float*)d_in[0];
    const float* neibs = (const float*)d_in[1];
    // d_in[2] edge_emb: dead code in reference, never read
    const float* mask  = (const float*)d_in[3];
    const float* axw1  = (const float*)d_in[4];
    const float* axb1  = (const float*)d_in[5];
    const float* axw2  = (const float*)d_in[6];
    const float* axb2  = (const float*)d_in[7];
    const float* anw1  = (const float*)d_in[8];
    const float* anb1  = (const float*)d_in[9];
    const float* anw2  = (const float*)d_in[10];
    const float* anb2  = (const float*)d_in[11];
    // d_in[12..15] ae_*: dead code
    const float* fcw   = (const float*)d_in[16];
    const float* fcb   = (const float*)d_in[17];
    float* out = (float*)d_out;

    k1_att<<<128, 256>>>(x, neibs, axw1, axb1, axw2, axb2,
                         anw1, anb1, anw2, anb2);
    k2_attn<<<(NROWS / TM2) * JSPLIT, 128>>>(neibs, mask);
    k3_fc<<<NROWS / TM, 256>>>(x, fcw, fcb, out);
}

// round 11
// speedup vs baseline: 1.6910x; 1.0263x over previous
#include <cuda_runtime.h>
#include <cuda_bf16.h>
#include <cstdint>

#define NROWS 2048
#define NN    2048
#define DIN   256
#define H     32
#define DOUT  256
#define TM    16      // k3 row tile
#define TM2   32      // k2 row tile
#define TN    32      // k2 neighbor chunk
#define JSPLIT 4
#define JCH   (NN / JSPLIT)   // 512 neighbors per CTA

// Scratch (no allocations allowed)
__device__ float g_xa[NROWS * H];
__device__ float g_na[NN * H];
__device__ float g_pnum[JSPLIT][NROWS * DIN];   // split-j partial numerators
__device__ float g_pden[JSPLIT][NROWS];         // split-j partial denominators

// ---------------------------------------------------------------------------
// MMA helpers (Ampere-style mma.sync, bf16 inputs, fp32 accum)
// ---------------------------------------------------------------------------
__device__ __forceinline__ uint32_t smem_u32(const void* p) {
    return (uint32_t)__cvta_generic_to_shared(p);
}
__device__ __forceinline__ void ldsm_x4(uint32_t& r0, uint32_t& r1,
                                        uint32_t& r2, uint32_t& r3, uint32_t a) {
    asm volatile("ldmatrix.sync.aligned.m8n8.x4.shared.b16 {%0,%1,%2,%3}, [%4];\n"
                 : "=r"(r0), "=r"(r1), "=r"(r2), "=r"(r3) : "r"(a));
}
__device__ __forceinline__ void ldsm_x2(uint32_t& r0, uint32_t& r1, uint32_t a) {
    asm volatile("ldmatrix.sync.aligned.m8n8.x2.shared.b16 {%0,%1}, [%2];\n"
                 : "=r"(r0), "=r"(r1) : "r"(a));
}
__device__ __forceinline__ void ldsm_x2t(uint32_t& r0, uint32_t& r1, uint32_t a) {
    asm volatile("ldmatrix.sync.aligned.m8n8.x2.trans.shared.b16 {%0,%1}, [%2];\n"
                 : "=r"(r0), "=r"(r1) : "r"(a));
}
__device__ __forceinline__ void mma_bf16(float* c, const uint32_t* a, const uint32_t* b) {
    asm volatile(
        "mma.sync.aligned.m16n8k16.row.col.f32.bf16.bf16.f32 "
        "{%0,%1,%2,%3}, {%4,%5,%6,%7}, {%8,%9}, {%0,%1,%2,%3};\n"
        : "+f"(c[0]), "+f"(c[1]), "+f"(c[2]), "+f"(c[3])
        : "r"(a[0]), "r"(a[1]), "r"(a[2]), "r"(a[3]), "r"(b[0]), "r"(b[1]));
}

// ---------------------------------------------------------------------------
// K1: att = tanh(x@W1+b1)@W2+b2 for x (ax_*) and neibs (an_*).
// 256 CTAs x 128 threads, 16 rows/CTA -> >=2 CTAs/SM so weight-load and
// compute phases of different CTAs overlap (fixes issue=13% latency bound).
// ---------------------------------------------------------------------------
__global__ __launch_bounds__(128) void k1_att(
    const float* __restrict__ x, const float* __restrict__ neibs,
    const float* __restrict__ axw1, const float* __restrict__ axb1,
    const float* __restrict__ axw2, const float* __restrict__ axb2,
    const float* __restrict__ anw1, const float* __restrict__ anb1,
    const float* __restrict__ anw2, const float* __restrict__ anb2)
{
    __shared__ float W1s[DIN * H];   // 32 KB
    __shared__ float W2s[H * H];     // 4 KB
    __shared__ float b1s[H], b2s[H];

    const int tid = threadIdx.x;
    const int cta = blockIdx.x;
    const bool isx = (cta < 128);
    const float* W1 = isx ? axw1 : anw1;
    const float* W2 = isx ? axw2 : anw2;
    const float* B1 = isx ? axb1 : anb1;
    const float* B2 = isx ? axb2 : anb2;
    const float* src = isx ? x : neibs;
    float* dst = isx ? g_xa : g_na;
    const int row0 = (cta & 127) * 16;

    for (int i = tid; i < DIN * H / 4; i += 128)
        ((float4*)W1s)[i] = ((const float4*)W1)[i];
    for (int i = tid; i < H * H / 4; i += 128)
        ((float4*)W2s)[i] = ((const float4*)W2)[i];
    if (tid < H) { b1s[tid] = B1[tid]; b2s[tid] = B2[tid]; }
    __syncthreads();

    const int w = tid >> 5, l = tid & 31;
    const float* rp[4];
#pragma unroll
    for (int i = 0; i < 4; i++)
        rp[i] = src + (size_t)(row0 + w * 4 + i) * DIN;

    float h1[4];
#pragma unroll
    for (int i = 0; i < 4; i++) h1[i] = b1s[l];

#pragma unroll 4
    for (int k = 0; k < DIN; k += 4) {
        float4 xv0 = *(const float4*)(rp[0] + k);
        float4 xv1 = *(const float4*)(rp[1] + k);
        float4 xv2 = *(const float4*)(rp[2] + k);
        float4 xv3 = *(const float4*)(rp[3] + k);
        float w0 = W1s[(k + 0) * H + l];
        float w1 = W1s[(k + 1) * H + l];
        float w2 = W1s[(k + 2) * H + l];
        float w3 = W1s[(k + 3) * H + l];
        h1[0] = fmaf(xv0.x, w0, h1[0]); h1[0] = fmaf(xv0.y, w1, h1[0]);
        h1[0] = fmaf(xv0.z, w2, h1[0]); h1[0] = fmaf(xv0.w, w3, h1[0]);
        h1[1] = fmaf(xv1.x, w0, h1[1]); h1[1] = fmaf(xv1.y, w1, h1[1]);
        h1[1] = fmaf(xv1.z, w2, h1[1]); h1[1] = fmaf(xv1.w, w3, h1[1]);
        h1[2] = fmaf(xv2.x, w0, h1[2]); h1[2] = fmaf(xv2.y, w1, h1[2]);
        h1[2] = fmaf(xv2.z, w2, h1[2]); h1[2] = fmaf(xv2.w, w3, h1[2]);
        h1[3] = fmaf(xv3.x, w0, h1[3]); h1[3] = fmaf(xv3.y, w1, h1[3]);
        h1[3] = fmaf(xv3.z, w2, h1[3]); h1[3] = fmaf(xv3.w, w3, h1[3]);
    }
#pragma unroll
    for (int i = 0; i < 4; i++) h1[i] = tanhf(h1[i]);

    float h2[4];
#pragma unroll
    for (int i = 0; i < 4; i++) h2[i] = b2s[l];
#pragma unroll
    for (int m = 0; m < H; m++) {
        float wv = W2s[m * H + l];
        h2[0] = fmaf(__shfl_sync(0xffffffffu, h1[0], m), wv, h2[0]);
        h2[1] = fmaf(__shfl_sync(0xffffffffu, h1[1], m), wv, h2[1]);
        h2[2] = fmaf(__shfl_sync(0xffffffffu, h1[2], m), wv, h2[2]);
        h2[3] = fmaf(__shfl_sync(0xffffffffu, h1[3], m), wv, h2[3]);
    }
#pragma unroll
    for (int i = 0; i < 4; i++)
        dst[(size_t)(row0 + w * 4 + i) * H + l] = h2[i];
}

// ---------------------------------------------------------------------------
// K2: fused masked-softmax attention on TENSOR CORES (mma.sync bf16).
// Grid = 256 CTAs (64 row-tiles x 4 j-quarters), 128 threads (4 warps).
// Per 32-j chunk: QK^T mma (warp owns 8 j-cols, all 32 rows), mask*s, exp
// (fp32), P -> smem bf16, then PV mma (warp owns 64 d-cols, all 32 rows).
// Strides 40 / 264 elems (odd multiples of 16B) -> conflict-free ldmatrix.
// ---------------------------------------------------------------------------
__global__ __launch_bounds__(128) void k2_attn(
    const float* __restrict__ neibs, const float* __restrict__ mask)
{
    __shared__ __align__(16) __nv_bfloat16 xa_s[TM2 * 40];
    __shared__ __align__(16) __nv_bfloat16 na_s[TN * 40];
    __shared__ __align__(16) __nv_bfloat16 V_s[TN * 264];
    __shared__ __align__(16) __nv_bfloat16 P_s[TM2 * 40];
    __shared__ float dsum[4][TM2];

    const int tid = threadIdx.x;
    const int w = tid >> 5, lane = tid & 31;
    const int g = lane >> 2, t = lane & 3;
    const int tile = blockIdx.x >> 2;
    const int jq   = blockIdx.x & 3;
    const int row0 = tile * TM2;
    const int jbase = jq * JCH;

    // stage xa (fp32 -> bf16), rows row0..row0+31
    for (int i = tid; i < 512; i += 128) {
        int r = i >> 4, kp = (i & 15) * 2;
        float2 v = *(const float2*)&g_xa[(size_t)(row0 + r) * H + kp];
        *(__nv_bfloat162*)&xa_s[r * 40 + kp] = __floats2bfloat162_rn(v.x, v.y);
    }

    float accv[2][8][4];
#pragma unroll
    for (int mt = 0; mt < 2; mt++)
#pragma unroll
        for (int nf = 0; nf < 8; nf++)
#pragma unroll
            for (int q = 0; q < 4; q++) accv[mt][nf][q] = 0.f;
    float dacc[2][2] = {0.f, 0.f, 0.f, 0.f};

    for (int j0 = 0; j0 < JCH; j0 += TN) {
        const int jg = jbase + j0;
        __syncthreads();   // previous chunk's PV reads of V_s/P_s done

        // stage na chunk (fp32 -> bf16)
        for (int i = tid; i < 512; i += 128) {
            int r = i >> 4, kp = (i & 15) * 2;
            float2 v = *(const float2*)&g_na[(size_t)(jg + r) * H + kp];
            *(__nv_bfloat162*)&na_s[r * 40 + kp] = __floats2bfloat162_rn(v.x, v.y);
        }
        // stage V chunk (neibs fp32 -> bf16)
        for (int i = tid; i < 2048; i += 128) {
            int r = i >> 6, c4 = (i & 63) * 4;
            float4 v = *(const float4*)&neibs[(size_t)(jg + r) * DIN + c4];
            *(__nv_bfloat162*)&V_s[r * 264 + c4]     = __floats2bfloat162_rn(v.x, v.y);
            *(__nv_bfloat162*)&V_s[r * 264 + c4 + 2] = __floats2bfloat162_rn(v.z, v.w);
        }
        __syncthreads();

        // ---- QK^T: s[32 x 32] ; warp w owns j-cols w*8..w*8+8 ----
        float sf[2][4];
#pragma unroll
        for (int mt = 0; mt < 2; mt++)
#pragma unroll
            for (int q = 0; q < 4; q++) sf[mt][q] = 0.f;

#pragma unroll
        for (int ks = 0; ks < H; ks += 16) {
            uint32_t b[2];
            ldsm_x2(b[0], b[1],
                smem_u32(&na_s[(w * 8 + (lane & 7)) * 40 + ks + ((lane >> 3) & 1) * 8]));
#pragma unroll
            for (int mt = 0; mt < 2; mt++) {
                uint32_t a[4];
                ldsm_x4(a[0], a[1], a[2], a[3],
                    smem_u32(&xa_s[(mt * 16 + (lane & 15)) * 40 + ks + (lane >> 4) * 8]));
                mma_bf16(sf[mt], a, b);
            }
        }

        // ---- mask * s, exp (fp32), P -> smem bf16, denominator accum ----
#pragma unroll
        for (int mt = 0; mt < 2; mt++) {
            int rlo = row0 + mt * 16 + g;
            const float* mlo_p = mask + (size_t)rlo * NN + jg + w * 8 + t * 2;
            const float* mhi_p = mask + (size_t)(rlo + 8) * NN + jg + w * 8 + t * 2;
            float2 mlo = *(const float2*)mlo_p;
            float2 mhi = *(const float2*)mhi_p;
            float p0 = __expf(sf[mt][0] * mlo.x);
            float p1 = __expf(sf[mt][1] * mlo.y);
            float p2 = __expf(sf[mt][2] * mhi.x);
            float p3 = __expf(sf[mt][3] * mhi.y);
            dacc[mt][0] += p0 + p1;
            dacc[mt][1] += p2 + p3;
            *(__nv_bfloat162*)&P_s[(mt * 16 + g) * 40 + w * 8 + t * 2] =
                __floats2bfloat162_rn(p0, p1);
            *(__nv_bfloat162*)&P_s[(mt * 16 + 8 + g) * 40 + w * 8 + t * 2] =
                __floats2bfloat162_rn(p2, p3);
        }
        __syncthreads();

        // ---- PV: acc[32 x 256] += P[32 x 32] @ V[32 x 256] ----
#pragma unroll
        for (int ks = 0; ks < TN; ks += 16) {
            uint32_t a0[4], a1[4];
            ldsm_x4(a0[0], a0[1], a0[2], a0[3],
                smem_u32(&P_s[((lane & 15)) * 40 + ks + (lane >> 4) * 8]));
            ldsm_x4(a1[0], a1[1], a1[2], a1[3],
                smem_u32(&P_s[(16 + (lane & 15)) * 40 + ks + (lane >> 4) * 8]));
#pragma unroll
            for (int nf = 0; nf < 8; nf++) {
                uint32_t b[2];
                ldsm_x2t(b[0], b[1],
                    smem_u32(&V_s[(ks + (lane & 15)) * 264 + w * 64 + nf * 8]));
                mma_bf16(accv[0][nf], a0, b);
                mma_bf16(accv[1][nf], a1, b);
            }
        }
    }

    // ---- denominators: reduce over t lanes, then across warps ----
#pragma unroll
    for (int off = 1; off <= 2; off <<= 1) {
        dacc[0][0] += __shfl_xor_sync(0xffffffffu, dacc[0][0], off);
        dacc[0][1] += __shfl_xor_sync(0xffffffffu, dacc[0][1], off);
        dacc[1][0] += __shfl_xor_sync(0xffffffffu, dacc[1][0], off);
        dacc[1][1] += __shfl_xor_sync(0xffffffffu, dacc[1][1], off);
    }
    if (t == 0) {
        dsum[w][g]      = dacc[0][0];
        dsum[w][8 + g]  = dacc[0][1];
        dsum[w][16 + g] = dacc[1][0];
        dsum[w][24 + g] = dacc[1][1];
    }
    __syncthreads();
    if (tid < TM2)
        g_pden[jq][row0 + tid] =
            dsum[0][tid] + dsum[1][tid] + dsum[2][tid] + dsum[3][tid];

    // ---- partial numerators ----
    float* np = &g_pnum[jq][0];
#pragma unroll
    for (int mt = 0; mt < 2; mt++) {
#pragma unroll
        for (int nf = 0; nf < 8; nf++) {
            int col = w * 64 + nf * 8 + t * 2;
            size_t blo = (size_t)(row0 + mt * 16 + g) * DIN + col;
            size_t bhi = (size_t)(row0 + mt * 16 + 8 + g) * DIN + col;
            *(float2*)&np[blo] = make_float2(accv[mt][nf][0], accv[mt][nf][1]);
            *(float2*)&np[bhi] = make_float2(accv[mt][nf][2], accv[mt][nf][3]);
        }
    }
}

// ---------------------------------------------------------------------------
// K3: out = sigmoid([x, agg] @ fcx_w + fcx_b); agg materialized on the fly
// from the 4 split-j partials. 128 CTAs x 16 rows, K=512.
// ---------------------------------------------------------------------------
__global__ __launch_bounds__(256) void k3_fc(
    const float* __restrict__ x, const float* __restrict__ fcw,
    const float* __restrict__ fcb, float* __restrict__ out)
{
    __shared__ float As[32][TM];      // [kk][r]
    __shared__ float Ws[32][DOUT];    // 32 KB
    __shared__ float bs[DOUT];
    __shared__ float invden[TM];

    const int tid = threadIdx.x;
    const int row0 = blockIdx.x * TM;
    bs[tid] = fcb[tid];
    if (tid < TM) {
        float d = g_pden[0][row0 + tid] + g_pden[1][row0 + tid]
                + g_pden[2][row0 + tid] + g_pden[3][row0 + tid];
        invden[tid] = 1.f / d;
    }

    float acc[4][4];
#pragma unroll
    for (int a = 0; a < 4; a++)
#pragma unroll
        for (int b = 0; b < 4; b++) acc[a][b] = 0.f;

    const int rg = tid >> 6, cg = tid & 63;

    for (int k0 = 0; k0 < 2 * DIN; k0 += 32) {
        for (int i = tid; i < TM * 32; i += 256) {
            int r = i & 15, kk = i >> 4;
            int k = k0 + kk;
            float v;
            if (k < DIN) {
                v = x[(size_t)(row0 + r) * DIN + k];
            } else {
                size_t idx = (size_t)(row0 + r) * DIN + (k - DIN);
                float n = g_pnum[0][idx] + g_pnum[1][idx]
                        + g_pnum[2][idx] + g_pnum[3][idx];
                v = 1.f / (1.f + __expf(-n * invden[r]));
            }
            As[kk][r] = v;
        }
        for (int i = tid; i < 32 * DOUT / 4; i += 256)
            ((float4*)Ws)[i] = ((const float4*)(fcw + (size_t)k0 * DOUT))[i];
        __syncthreads();

#pragma unroll 8
        for (int kk = 0; kk < 32; kk++) {
            float4 a4 = *(const float4*)&As[kk][rg * 4];
            float4 w4 = *(const float4*)&Ws[kk][cg * 4];
            acc[0][0] = fmaf(a4.x, w4.x, acc[0][0]);
            acc[0][1] = fmaf(a4.x, w4.y, acc[0][1]);
            acc[0][2] = fmaf(a4.x, w4.z, acc[0][2]);
            acc[0][3] = fmaf(a4.x, w4.w, acc[0][3]);
            acc[1][0] = fmaf(a4.y, w4.x, acc[1][0]);
            acc[1][1] = fmaf(a4.y, w4.y, acc[1][1]);
            acc[1][2] = fmaf(a4.y, w4.z, acc[1][2]);
            acc[1][3] = fmaf(a4.y, w4.w, acc[1][3]);
            acc[2][0] = fmaf(a4.z, w4.x, acc[2][0]);
            acc[2][1] = fmaf(a4.z, w4.y, acc[2][1]);
            acc[2][2] = fmaf(a4.z, w4.z, acc[2][2]);
            acc[2][3] = fmaf(a4.z, w4.w, acc[2][3]);
            acc[3][0] = fmaf(a4.w, w4.x, acc[3][0]);
            acc[3][1] = fmaf(a4.w, w4.y, acc[3][1]);
            acc[3][2] = fmaf(a4.w, w4.z, acc[3][2]);
            acc[3][3] = fmaf(a4.w, w4.w, acc[3][3]);
        }
        __syncthreads();
    }

#pragma unroll
    for (int a = 0; a < 4; a++) {
        int r = row0 + rg * 4 + a;
        float4 o;
        o.x = 1.f / (1.f + __expf(-(acc[a][0] + bs[cg * 4 + 0])));
        o.y = 1.f / (1.f + __expf(-(acc[a][1] + bs[cg * 4 + 1])));
        o.z = 1.f / (1.f + __expf(-(acc[a][2] + bs[cg * 4 + 2])));
        o.w = 1.f / (1.f + __expf(-(acc[a][3] + bs[cg * 4 + 3])));
        *(float4*)&out[(size_t)r * DOUT + cg * 4] = o;
    }
}

// ---------------------------------------------------------------------------
extern "C" void kernel_launch(void* const* d_in, const int* in_sizes, int n_in,
                              void* d_out, int out_size) {
    const float* x     = (const float*)d_in[0];
    const float* neibs = (const float*)d_in[1];
    // d_in[2] edge_emb: dead code in reference, never read
    const float* mask  = (const float*)d_in[3];
    const float* axw1  = (const float*)d_in[4];
    const float* axb1  = (const float*)d_in[5];
    const float* axw2  = (const float*)d_in[6];
    const float* axb2  = (const float*)d_in[7];
    const float* anw1  = (const float*)d_in[8];
    const float* anb1  = (const float*)d_in[9];
    const float* anw2  = (const float*)d_in[10];
    const float* anb2  = (const float*)d_in[11];
    // d_in[12..15] ae_*: dead code
    const float* fcw   = (const float*)d_in[16];
    const float* fcb   = (const float*)d_in[17];
    float* out = (float*)d_out;

    k1_att<<<256, 128>>>(x, neibs, axw1, axb1, axw2, axb2,
                         anw1, anb1, anw2, anb2);
    k2_attn<<<(NROWS / TM2) * JSPLIT, 128>>>(neibs, mask);
    k3_fc<<<NROWS / TM, 256>>>(x, fcw, fcb, out);
}

// round 14
// speedup vs baseline: 3.6560x; 2.1621x over previous
#include <cuda_runtime.h>
#include <cuda_bf16.h>
#include <cstdint>

#define NROWS 2048
#define NN    2048
#define DIN   256
#define H     32
#define DOUT  256
#define TM    16      // k3 row tile
#define TM2   32      // k2 row tile
#define TN    32      // k2 neighbor chunk
#define JSPLIT 8
#define JCH   (NN / JSPLIT)   // 256 neighbors per CTA
#define NCH   (JCH / TN)      // 8 chunks per CTA

// Scratch (no allocations allowed)
__device__ __align__(16) __nv_bfloat16 g_xa16[NROWS * H];
__device__ __align__(16) __nv_bfloat16 g_na16[NN * H];
__device__ __align__(16) __nv_bfloat16 g_nb16[NN * DIN];     // neibs in bf16
__device__ float g_pnum[JSPLIT][NROWS * DIN];                // partial numerators
__device__ float g_pden[JSPLIT][NROWS];                      // partial denominators

// ---------------------------------------------------------------------------
// helpers
// ---------------------------------------------------------------------------
__device__ __forceinline__ uint32_t smem_u32(const void* p) {
    return (uint32_t)__cvta_generic_to_shared(p);
}
__device__ __forceinline__ void ldsm_x4(uint32_t& r0, uint32_t& r1,
                                        uint32_t& r2, uint32_t& r3, uint32_t a) {
    asm volatile("ldmatrix.sync.aligned.m8n8.x4.shared.b16 {%0,%1,%2,%3}, [%4];\n"
                 : "=r"(r0), "=r"(r1), "=r"(r2), "=r"(r3) : "r"(a));
}
__device__ __forceinline__ void ldsm_x2(uint32_t& r0, uint32_t& r1, uint32_t a) {
    asm volatile("ldmatrix.sync.aligned.m8n8.x2.shared.b16 {%0,%1}, [%2];\n"
                 : "=r"(r0), "=r"(r1) : "r"(a));
}
__device__ __forceinline__ void ldsm_x2t(uint32_t& r0, uint32_t& r1, uint32_t a) {
    asm volatile("ldmatrix.sync.aligned.m8n8.x2.trans.shared.b16 {%0,%1}, [%2];\n"
                 : "=r"(r0), "=r"(r1) : "r"(a));
}
__device__ __forceinline__ void mma_bf16(float* c, const uint32_t* a, const uint32_t* b) {
    asm volatile(
        "mma.sync.aligned.m16n8k16.row.col.f32.bf16.bf16.f32 "
        "{%0,%1,%2,%3}, {%4,%5,%6,%7}, {%8,%9}, {%0,%1,%2,%3};\n"
        : "+f"(c[0]), "+f"(c[1]), "+f"(c[2]), "+f"(c[3])
        : "r"(a[0]), "r"(a[1]), "r"(a[2]), "r"(a[3]), "r"(b[0]), "r"(b[1]));
}
__device__ __forceinline__ void cp16(uint32_t dst, const void* src) {
    asm volatile("cp.async.cg.shared.global [%0], [%1], 16;\n" :: "r"(dst), "l"(src));
}
__device__ __forceinline__ void cp_commit() {
    asm volatile("cp.async.commit_group;\n");
}
template <int N>
__device__ __forceinline__ void cp_wait() {
    asm volatile("cp.async.wait_group %0;\n" :: "n"(N));
}

// ---------------------------------------------------------------------------
// K1: att = tanh(x@W1+b1)@W2+b2 for x (ax_*) and neibs (an_*), outputs bf16.
// Neibs path also converts its feature rows to bf16 (g_nb16) for k2's TMA-
// style cp.async staging. 512 CTAs x 128 thr, 8 rows/CTA; rows staged to
// smem first so the FMA loop has NO global loads (fixes issue=15% stall).
// ---------------------------------------------------------------------------
__global__ __launch_bounds__(128) void k1_att(
    const float* __restrict__ x, const float* __restrict__ neibs,
    const float* __restrict__ axw1, const float* __restrict__ axb1,
    const float* __restrict__ axw2, const float* __restrict__ axb2,
    const float* __restrict__ anw1, const float* __restrict__ anb1,
    const float* __restrict__ anw2, const float* __restrict__ anb2)
{
    __shared__ float W1s[DIN * H];     // 32 KB
    __shared__ float W2s[H * H];       // 4 KB
    __shared__ float b1s[H], b2s[H];
    __shared__ float rows_s[8 * DIN];  // 8 KB

    const int tid = threadIdx.x;
    const int cta = blockIdx.x;
    const bool isx = (cta < 256);
    const float* W1 = isx ? axw1 : anw1;
    const float* W2 = isx ? axw2 : anw2;
    const float* B1 = isx ? axb1 : anb1;
    const float* B2 = isx ? axb2 : anb2;
    const float* src = isx ? x : neibs;
    __nv_bfloat16* dst = isx ? g_xa16 : g_na16;
    const int row0 = (cta & 255) * 8;

    for (int i = tid; i < DIN * H / 4; i += 128)
        ((float4*)W1s)[i] = ((const float4*)W1)[i];
    for (int i = tid; i < H * H / 4; i += 128)
        ((float4*)W2s)[i] = ((const float4*)W2)[i];
    if (tid < H) { b1s[tid] = B1[tid]; b2s[tid] = B2[tid]; }
    for (int i = tid; i < 8 * DIN / 4; i += 128)
        ((float4*)rows_s)[i] = ((const float4*)(src + (size_t)row0 * DIN))[i];
    __syncthreads();

    // neibs path: emit bf16 copy of these 8 feature rows
    if (!isx) {
        __nv_bfloat162* nb2p = (__nv_bfloat162*)g_nb16 + (size_t)row0 * DIN / 2;
        for (int i = tid; i < 8 * DIN / 2; i += 128) {
            float2 v = *(const float2*)&rows_s[i * 2];
            nb2p[i] = __floats2bfloat162_rn(v.x, v.y);
        }
    }

    const int w = tid >> 5, l = tid & 31;
    const float* r0p = &rows_s[(w * 2 + 0) * DIN];
    const float* r1p = &rows_s[(w * 2 + 1) * DIN];

    float h1a0 = b1s[l], h1b0 = 0.f, h1a1 = b1s[l], h1b1 = 0.f;
#pragma unroll 8
    for (int k = 0; k < DIN; k += 4) {
        float4 x0 = *(const float4*)(r0p + k);
        float4 x1 = *(const float4*)(r1p + k);
        float w0 = W1s[(k + 0) * H + l];
        float w1 = W1s[(k + 1) * H + l];
        float w2 = W1s[(k + 2) * H + l];
        float w3 = W1s[(k + 3) * H + l];
        h1a0 = fmaf(x0.x, w0, h1a0); h1b0 = fmaf(x0.z, w2, h1b0);
        h1a0 = fmaf(x0.y, w1, h1a0); h1b0 = fmaf(x0.w, w3, h1b0);
        h1a1 = fmaf(x1.x, w0, h1a1); h1b1 = fmaf(x1.z, w2, h1b1);
        h1a1 = fmaf(x1.y, w1, h1a1); h1b1 = fmaf(x1.w, w3, h1b1);
    }
    float h1_0 = tanhf(h1a0 + h1b0);
    float h1_1 = tanhf(h1a1 + h1b1);

    float h2_0 = b2s[l], h2_1 = b2s[l];
#pragma unroll
    for (int m = 0; m < H; m++) {
        float wv = W2s[m * H + l];
        h2_0 = fmaf(__shfl_sync(0xffffffffu, h1_0, m), wv, h2_0);
        h2_1 = fmaf(__shfl_sync(0xffffffffu, h1_1, m), wv, h2_1);
    }
    dst[(size_t)(row0 + w * 2 + 0) * H + l] = __float2bfloat16(h2_0);
    dst[(size_t)(row0 + w * 2 + 1) * H + l] = __float2bfloat16(h2_1);
}

// ---------------------------------------------------------------------------
// K2: fused masked-softmax attention on tensor cores, cp.async double-buffered.
// Grid = 512 CTAs (64 row-tiles x 8 j-splits), 128 threads (4 warps).
// All bf16 sources precomputed by k1; chunk c+1 streams in while c computes.
// ---------------------------------------------------------------------------
__global__ __launch_bounds__(128) void k2_attn(const float* __restrict__ mask)
{
    __shared__ __align__(16) __nv_bfloat16 xa_s[TM2 * 40];        // 2.5 KB
    __shared__ __align__(16) __nv_bfloat16 na_s[2][TN * 40];      // 5 KB
    __shared__ __align__(16) __nv_bfloat16 V_s[2][TN * 264];      // 33 KB
    __shared__ __align__(16) __nv_bfloat16 P_s[TM2 * 40];         // 2.5 KB
    __shared__ float dsum[4][TM2];

    const int tid = threadIdx.x;
    const int w = tid >> 5, lane = tid & 31;
    const int g = lane >> 2, t = lane & 3;
    const int tile = blockIdx.x >> 3;
    const int jq   = blockIdx.x & 7;
    const int row0 = tile * TM2;
    const int jbase = jq * JCH;

    auto stage = [&](int c) {
        int b = c & 1;
        int jg = jbase + c * TN;
        { // na tile: 32 rows x 64B
            int r = tid >> 2, q = tid & 3;
            cp16(smem_u32(&na_s[b][r * 40 + q * 8]),
                 &g_na16[(size_t)(jg + r) * H + q * 8]);
        }
        // V tile: 32 rows x 512B
#pragma unroll
        for (int i = 0; i < 8; i++) {
            int idx = tid + i * 128;
            int r = idx >> 5, q = idx & 31;
            cp16(smem_u32(&V_s[b][r * 264 + q * 8]),
                 &g_nb16[(size_t)(jg + r) * DIN + q * 8]);
        }
        cp_commit();
    };

    // prologue: xa (once) + chunk 0 in group 0
    {
        int r = tid >> 2, q = tid & 3;
        cp16(smem_u32(&xa_s[r * 40 + q * 8]),
             &g_xa16[(size_t)(row0 + r) * H + q * 8]);
    }
    stage(0);

    float accv[2][8][4];
#pragma unroll
    for (int mt = 0; mt < 2; mt++)
#pragma unroll
        for (int nf = 0; nf < 8; nf++)
#pragma unroll
            for (int q = 0; q < 4; q++) accv[mt][nf][q] = 0.f;
    float dacc[2][2] = {0.f, 0.f, 0.f, 0.f};

    for (int c = 0; c < NCH; c++) {
        const int b = c & 1;
        const int jg = jbase + c * TN;

        if (c + 1 < NCH) { stage(c + 1); cp_wait<1>(); }
        else             { cp_wait<0>(); }
        __syncthreads();

        // prefetch mask fragments (fp32 LDG, hidden under QK mmas)
        float2 mlo[2], mhi[2];
#pragma unroll
        for (int mt = 0; mt < 2; mt++) {
            int rlo = row0 + mt * 16 + g;
            mlo[mt] = *(const float2*)(mask + (size_t)rlo * NN + jg + w * 8 + t * 2);
            mhi[mt] = *(const float2*)(mask + (size_t)(rlo + 8) * NN + jg + w * 8 + t * 2);
        }

        // ---- QK^T: s[32 x 32]; warp w owns j-cols w*8..w*8+7 ----
        float sf[2][4];
#pragma unroll
        for (int mt = 0; mt < 2; mt++)
#pragma unroll
            for (int q = 0; q < 4; q++) sf[mt][q] = 0.f;

#pragma unroll
        for (int ks = 0; ks < H; ks += 16) {
            uint32_t bb[2];
            ldsm_x2(bb[0], bb[1],
                smem_u32(&na_s[b][(w * 8 + (lane & 7)) * 40 + ks + ((lane >> 3) & 1) * 8]));
#pragma unroll
            for (int mt = 0; mt < 2; mt++) {
                uint32_t a[4];
                ldsm_x4(a[0], a[1], a[2], a[3],
                    smem_u32(&xa_s[(mt * 16 + (lane & 15)) * 40 + ks + (lane >> 4) * 8]));
                mma_bf16(sf[mt], a, bb);
            }
        }

        // ---- mask*s, exp (fp32), P -> smem bf16, denominator accum ----
#pragma unroll
        for (int mt = 0; mt < 2; mt++) {
            float p0 = __expf(sf[mt][0] * mlo[mt].x);
            float p1 = __expf(sf[mt][1] * mlo[mt].y);
            float p2 = __expf(sf[mt][2] * mhi[mt].x);
            float p3 = __expf(sf[mt][3] * mhi[mt].y);
            dacc[mt][0] += p0 + p1;
            dacc[mt][1] += p2 + p3;
            *(__nv_bfloat162*)&P_s[(mt * 16 + g) * 40 + w * 8 + t * 2] =
                __floats2bfloat162_rn(p0, p1);
            *(__nv_bfloat162*)&P_s[(mt * 16 + 8 + g) * 40 + w * 8 + t * 2] =
                __floats2bfloat162_rn(p2, p3);
        }
        __syncthreads();

        // ---- PV: acc[32 x 256] += P[32 x 32] @ V[32 x 256] ----
#pragma unroll
        for (int ks = 0; ks < TN; ks += 16) {
            uint32_t a0[4], a1[4];
            ldsm_x4(a0[0], a0[1], a0[2], a0[3],
                smem_u32(&P_s[(lane & 15) * 40 + ks + (lane >> 4) * 8]));
            ldsm_x4(a1[0], a1[1], a1[2], a1[3],
                smem_u32(&P_s[(16 + (lane & 15)) * 40 + ks + (lane >> 4) * 8]));
#pragma unroll
            for (int nf = 0; nf < 8; nf++) {
                uint32_t bb[2];
                ldsm_x2t(bb[0], bb[1],
                    smem_u32(&V_s[b][(ks + (lane & 15)) * 264 + w * 64 + nf * 8]));
                mma_bf16(accv[0][nf], a0, bb);
                mma_bf16(accv[1][nf], a1, bb);
            }
        }
        __syncthreads();   // protect V_s[b]/P_s before next stage/softmax
    }

    // ---- denominators: reduce over t lanes, then across warps ----
#pragma unroll
    for (int off = 1; off <= 2; off <<= 1) {
        dacc[0][0] += __shfl_xor_sync(0xffffffffu, dacc[0][0], off);
        dacc[0][1] += __shfl_xor_sync(0xffffffffu, dacc[0][1], off);
        dacc[1][0] += __shfl_xor_sync(0xffffffffu, dacc[1][0], off);
        dacc[1][1] += __shfl_xor_sync(0xffffffffu, dacc[1][1], off);
    }
    if (t == 0) {
        dsum[w][g]      = dacc[0][0];
        dsum[w][8 + g]  = dacc[0][1];
        dsum[w][16 + g] = dacc[1][0];
        dsum[w][24 + g] = dacc[1][1];
    }
    __syncthreads();
    if (tid < TM2)
        g_pden[jq][row0 + tid] =
            dsum[0][tid] + dsum[1][tid] + dsum[2][tid] + dsum[3][tid];

    // ---- partial numerators ----
    float* np = &g_pnum[jq][0];
#pragma unroll
    for (int mt = 0; mt < 2; mt++) {
#pragma unroll
        for (int nf = 0; nf < 8; nf++) {
            int col = w * 64 + nf * 8 + t * 2;
            size_t blo = (size_t)(row0 + mt * 16 + g) * DIN + col;
            size_t bhi = (size_t)(row0 + mt * 16 + 8 + g) * DIN + col;
            *(float2*)&np[blo] = make_float2(accv[mt][nf][0], accv[mt][nf][1]);
            *(float2*)&np[bhi] = make_float2(accv[mt][nf][2], accv[mt][nf][3]);
        }
    }
}

// ---------------------------------------------------------------------------
// K3: out = sigmoid([x, agg] @ fcx_w + fcx_b); agg materialized on the fly
// from the 8 split-j partials. 128 CTAs x 16 rows, K=512.
// ---------------------------------------------------------------------------
__global__ __launch_bounds__(256) void k3_fc(
    const float* __restrict__ x, const float* __restrict__ fcw,
    const float* __restrict__ fcb, float* __restrict__ out)
{
    __shared__ float As[32][TM];      // [kk][r]
    __shared__ float Ws[32][DOUT];    // 32 KB
    __shared__ float bs[DOUT];
    __shared__ float invden[TM];

    const int tid = threadIdx.x;
    const int row0 = blockIdx.x * TM;
    bs[tid] = fcb[tid];
    if (tid < TM) {
        float d = 0.f;
#pragma unroll
        for (int p = 0; p < JSPLIT; p++) d += g_pden[p][row0 + tid];
        invden[tid] = 1.f / d;
    }

    float acc[4][4];
#pragma unroll
    for (int a = 0; a < 4; a++)
#pragma unroll
        for (int b = 0; b < 4; b++) acc[a][b] = 0.f;

    const int rg = tid >> 6, cg = tid & 63;

    for (int k0 = 0; k0 < 2 * DIN; k0 += 32) {
        for (int i = tid; i < TM * 32; i += 256) {
            int r = i & 15, kk = i >> 4;
            int k = k0 + kk;
            float v;
            if (k < DIN) {
                v = x[(size_t)(row0 + r) * DIN + k];
            } else {
                size_t idx = (size_t)(row0 + r) * DIN + (k - DIN);
                float n = 0.f;
#pragma unroll
                for (int p = 0; p < JSPLIT; p++) n += g_pnum[p][idx];
                v = 1.f / (1.f + __expf(-n * invden[r]));
            }
            As[kk][r] = v;
        }
        for (int i = tid; i < 32 * DOUT / 4; i += 256)
            ((float4*)Ws)[i] = ((const float4*)(fcw + (size_t)k0 * DOUT))[i];
        __syncthreads();

#pragma unroll 8
        for (int kk = 0; kk < 32; kk++) {
            float4 a4 = *(const float4*)&As[kk][rg * 4];
            float4 w4 = *(const float4*)&Ws[kk][cg * 4];
            acc[0][0] = fmaf(a4.x, w4.x, acc[0][0]);
            acc[0][1] = fmaf(a4.x, w4.y, acc[0][1]);
            acc[0][2] = fmaf(a4.x, w4.z, acc[0][2]);
            acc[0][3] = fmaf(a4.x, w4.w, acc[0][3]);
            acc[1][0] = fmaf(a4.y, w4.x, acc[1][0]);
            acc[1][1] = fmaf(a4.y, w4.y, acc[1][1]);
            acc[1][2] = fmaf(a4.y, w4.z, acc[1][2]);
            acc[1][3] = fmaf(a4.y, w4.w, acc[1][3]);
            acc[2][0] = fmaf(a4.z, w4.x, acc[2][0]);
            acc[2][1] = fmaf(a4.z, w4.y, acc[2][1]);
            acc[2][2] = fmaf(a4.z, w4.z, acc[2][2]);
            acc[2][3] = fmaf(a4.z, w4.w, acc[2][3]);
            acc[3][0] = fmaf(a4.w, w4.x, acc[3][0]);
            acc[3][1] = fmaf(a4.w, w4.y, acc[3][1]);
            acc[3][2] = fmaf(a4.w, w4.z, acc[3][2]);
            acc[3][3] = fmaf(a4.w, w4.w, acc[3][3]);
        }
        __syncthreads();
    }

#pragma unroll
    for (int a = 0; a < 4; a++) {
        int r = row0 + rg * 4 + a;
        float4 o;
        o.x = 1.f / (1.f + __expf(-(acc[a][0] + bs[cg * 4 + 0])));
        o.y = 1.f / (1.f + __expf(-(acc[a][1] + bs[cg * 4 + 1])));
        o.z = 1.f / (1.f + __expf(-(acc[a][2] + bs[cg * 4 + 2])));
        o.w = 1.f / (1.f + __expf(-(acc[a][3] + bs[cg * 4 + 3])));
        *(float4*)&out[(size_t)r * DOUT + cg * 4] = o;
    }
}

// ---------------------------------------------------------------------------
extern "C" void kernel_launch(void* const* d_in, const int* in_sizes, int n_in,
                              void* d_out, int out_size) {
    const float* x     = (const float*)d_in[0];
    const float* neibs = (const float*)d_in[1];
    // d_in[2] edge_emb: dead code in reference, never read
    const float* mask  = (const float*)d_in[3];
    const float* axw1  = (const float*)d_in[4];
    const float* axb1  = (const float*)d_in[5];
    const float* axw2  = (const float*)d_in[6];
    const float* axb2  = (const float*)d_in[7];
    const float* anw1  = (const float*)d_in[8];
    const float* anb1  = (const float*)d_in[9];
    const float* anw2  = (const float*)d_in[10];
    const float* anb2  = (const float*)d_in[11];
    // d_in[12..15] ae_*: dead code
    const float* fcw   = (const float*)d_in[16];
    const float* fcb   = (const float*)d_in[17];
    float* out = (float*)d_out;

    k1_att<<<512, 128>>>(x, neibs, axw1, axb1, axw2, axb2,
                         anw1, anb1, anw2, anb2);
    k2_attn<<<(NROWS / TM2) * JSPLIT, 128>>>(mask);
    k3_fc<<<NROWS / TM, 256>>>(x, fcw, fcb, out);
}

// round 15
// speedup vs baseline: 3.8837x; 1.0623x over previous
#include <cuda_runtime.h>
#include <cuda_bf16.h>
#include <cstdint>

#define NROWS 2048
#define NN    2048
#define DIN   256
#define H     32
#define DOUT  256
#define TM    16      // k3 row tile
#define TM2   64      // k2 row tile
#define TN    32      // k2 neighbor chunk
#define JSPLIT 8
#define JCH   (NN / JSPLIT)   // 256 neighbors per CTA
#define NCH   (JCH / TN)      // 8 chunks per CTA

// Scratch (no allocations allowed)
__device__ __align__(16) __nv_bfloat16 g_xa16[NROWS * H];
__device__ __align__(16) __nv_bfloat16 g_na16[NN * H];
__device__ __align__(16) __nv_bfloat16 g_nb16[NN * DIN];     // neibs in bf16
__device__ float g_pnum[JSPLIT][NROWS * DIN];                // partial numerators
__device__ float g_pden[JSPLIT][NROWS];                      // partial denominators

// ---------------------------------------------------------------------------
// helpers
// ---------------------------------------------------------------------------
__device__ __forceinline__ uint32_t smem_u32(const void* p) {
    return (uint32_t)__cvta_generic_to_shared(p);
}
__device__ __forceinline__ void ldsm_x4(uint32_t& r0, uint32_t& r1,
                                        uint32_t& r2, uint32_t& r3, uint32_t a) {
    asm volatile("ldmatrix.sync.aligned.m8n8.x4.shared.b16 {%0,%1,%2,%3}, [%4];\n"
                 : "=r"(r0), "=r"(r1), "=r"(r2), "=r"(r3) : "r"(a));
}
__device__ __forceinline__ void ldsm_x2(uint32_t& r0, uint32_t& r1, uint32_t a) {
    asm volatile("ldmatrix.sync.aligned.m8n8.x2.shared.b16 {%0,%1}, [%2];\n"
                 : "=r"(r0), "=r"(r1) : "r"(a));
}
__device__ __forceinline__ void ldsm_x2t(uint32_t& r0, uint32_t& r1, uint32_t a) {
    asm volatile("ldmatrix.sync.aligned.m8n8.x2.trans.shared.b16 {%0,%1}, [%2];\n"
                 : "=r"(r0), "=r"(r1) : "r"(a));
}
__device__ __forceinline__ void mma_bf16(float* c, const uint32_t* a, const uint32_t* b) {
    asm volatile(
        "mma.sync.aligned.m16n8k16.row.col.f32.bf16.bf16.f32 "
        "{%0,%1,%2,%3}, {%4,%5,%6,%7}, {%8,%9}, {%0,%1,%2,%3};\n"
        : "+f"(c[0]), "+f"(c[1]), "+f"(c[2]), "+f"(c[3])
        : "r"(a[0]), "r"(a[1]), "r"(a[2]), "r"(a[3]), "r"(b[0]), "r"(b[1]));
}
__device__ __forceinline__ void cp16(uint32_t dst, const void* src) {
    asm volatile("cp.async.cg.shared.global [%0], [%1], 16;\n" :: "r"(dst), "l"(src));
}
__device__ __forceinline__ void cp_commit() {
    asm volatile("cp.async.commit_group;\n");
}
template <int N>
__device__ __forceinline__ void cp_wait() {
    asm volatile("cp.async.wait_group %0;\n" :: "n"(N));
}

// ---------------------------------------------------------------------------
// K1: att = tanh(x@W1+b1)@W2+b2 for x (ax_*) and neibs (an_*), outputs bf16.
// 256 CTAs x 256 thr x 16 rows. Rows staged via cp.async overlapping the W1
// loads; W2 + biases live in registers (unrolled) so smem = 48 KB exactly.
// Neibs path also emits the bf16 feature copy (g_nb16).
// ---------------------------------------------------------------------------
__global__ __launch_bounds__(256) void k1_att(
    const float* __restrict__ x, const float* __restrict__ neibs,
    const float* __restrict__ axw1, const float* __restrict__ axb1,
    const float* __restrict__ axw2, const float* __restrict__ axb2,
    const float* __restrict__ anw1, const float* __restrict__ anb1,
    const float* __restrict__ anw2, const float* __restrict__ anb2)
{
    __shared__ float W1s[DIN * H];       // 32 KB
    __shared__ float rows_s[16 * DIN];   // 16 KB

    const int tid = threadIdx.x;
    const int cta = blockIdx.x;
    const bool isx = (cta < 128);
    const float* W1 = isx ? axw1 : anw1;
    const float* W2 = isx ? axw2 : anw2;
    const float* B1 = isx ? axb1 : anb1;
    const float* B2 = isx ? axb2 : anb2;
    const float* src = isx ? x : neibs;
    __nv_bfloat16* dst = isx ? g_xa16 : g_na16;
    const int row0 = (cta & 127) * 16;
    const int w = tid >> 5, l = tid & 31;

    // rows via cp.async (non-blocking, overlaps the weight LDG latency)
#pragma unroll
    for (int i = 0; i < 4; i++) {
        int idx = tid + i * 256;               // 1024 x 16B = 16 KB
        cp16(smem_u32(&rows_s[idx * 4]),
             src + (size_t)row0 * DIN + idx * 4);
    }
    cp_commit();

    // W1 via regular LDG (L2-hot after first wave)
    for (int i = tid; i < DIN * H / 4; i += 256)
        ((float4*)W1s)[i] = ((const float4*)W1)[i];

    // W2 column + biases in registers
    float wreg[H];
#pragma unroll
    for (int m = 0; m < H; m++) wreg[m] = W2[m * H + l];
    float b1v = B1[l], b2v = B2[l];

    cp_wait<0>();
    __syncthreads();

    // neibs path: emit bf16 copy of these 16 feature rows (reads hot smem)
    if (!isx) {
        __nv_bfloat162* nb2p = (__nv_bfloat162*)g_nb16 + (size_t)row0 * DIN / 2;
        for (int i = tid; i < 16 * DIN / 2; i += 256) {
            float2 v = *(const float2*)&rows_s[i * 2];
            nb2p[i] = __floats2bfloat162_rn(v.x, v.y);
        }
    }

    const float* r0p = &rows_s[(w * 2 + 0) * DIN];
    const float* r1p = &rows_s[(w * 2 + 1) * DIN];

    float h1a0 = b1v, h1b0 = 0.f, h1a1 = b1v, h1b1 = 0.f;
#pragma unroll 8
    for (int k = 0; k < DIN; k += 4) {
        float4 x0 = *(const float4*)(r0p + k);
        float4 x1 = *(const float4*)(r1p + k);
        float w0 = W1s[(k + 0) * H + l];
        float w1 = W1s[(k + 1) * H + l];
        float w2 = W1s[(k + 2) * H + l];
        float w3 = W1s[(k + 3) * H + l];
        h1a0 = fmaf(x0.x, w0, h1a0); h1b0 = fmaf(x0.z, w2, h1b0);
        h1a0 = fmaf(x0.y, w1, h1a0); h1b0 = fmaf(x0.w, w3, h1b0);
        h1a1 = fmaf(x1.x, w0, h1a1); h1b1 = fmaf(x1.z, w2, h1b1);
        h1a1 = fmaf(x1.y, w1, h1a1); h1b1 = fmaf(x1.w, w3, h1b1);
    }
    float h1_0 = tanhf(h1a0 + h1b0);
    float h1_1 = tanhf(h1a1 + h1b1);

    float h2_0 = b2v, h2_1 = b2v;
#pragma unroll
    for (int m = 0; m < H; m++) {
        h2_0 = fmaf(__shfl_sync(0xffffffffu, h1_0, m), wreg[m], h2_0);
        h2_1 = fmaf(__shfl_sync(0xffffffffu, h1_1, m), wreg[m], h2_1);
    }
    dst[(size_t)(row0 + w * 2 + 0) * H + l] = __float2bfloat16(h2_0);
    dst[(size_t)(row0 + w * 2 + 1) * H + l] = __float2bfloat16(h2_1);
}

// ---------------------------------------------------------------------------
// K2: fused masked-softmax attention, tensor cores, cp.async double-buffered.
// TM2=64 rows/CTA, 8 warps. Grid = 256 CTAs (32 row-tiles x 8 j-splits).
// QK: warp (wm,wj) owns rows wm*32..+31, j-cols wj*8..+7.
// PV: warp w owns cols w*32..+31, all 64 rows.
// dsum aliases P_s (used only after final PV) -> static smem = 48 KB exactly.
// ---------------------------------------------------------------------------
__global__ __launch_bounds__(256) void k2_attn(const float* __restrict__ mask)
{
    __shared__ __align__(16) __nv_bfloat16 xa_s[TM2 * 40];        // 5 KB
    __shared__ __align__(16) __nv_bfloat16 na_s[2][TN * 40];      // 5 KB
    __shared__ __align__(16) __nv_bfloat16 V_s[2][TN * 264];      // 33 KB
    __shared__ __align__(16) __nv_bfloat16 P_s[TM2 * 40];         // 5 KB

    const int tid = threadIdx.x;
    const int w = tid >> 5, lane = tid & 31;
    const int g = lane >> 2, t = lane & 3;
    const int wj = w & 3, wm = w >> 2;          // QK ownership
    const int tile = blockIdx.x >> 3;
    const int jq   = blockIdx.x & 7;
    const int row0 = tile * TM2;
    const int jbase = jq * JCH;

    auto stage = [&](int c) {
        int b = c & 1;
        int jg = jbase + c * TN;
        if (tid < 128) {  // na tile: 32 rows x 64B = 128 cp16
            int r = tid >> 2, q = tid & 3;
            cp16(smem_u32(&na_s[b][r * 40 + q * 8]),
                 &g_na16[(size_t)(jg + r) * H + q * 8]);
        }
        // V tile: 32 rows x 512B = 1024 cp16
#pragma unroll
        for (int i = 0; i < 4; i++) {
            int idx = tid + i * 256;
            int r = idx >> 5, q = idx & 31;
            cp16(smem_u32(&V_s[b][r * 264 + q * 8]),
                 &g_nb16[(size_t)(jg + r) * DIN + q * 8]);
        }
        cp_commit();
    };

    // prologue: xa (64 rows x 64B = 256 cp16) + chunk 0, one group
    {
        int r = tid >> 2, q = tid & 3;
        cp16(smem_u32(&xa_s[r * 40 + q * 8]),
             &g_xa16[(size_t)(row0 + r) * H + q * 8]);
    }
    stage(0);

    float accv[4][4][4];
#pragma unroll
    for (int mt = 0; mt < 4; mt++)
#pragma unroll
        for (int nf = 0; nf < 4; nf++)
#pragma unroll
            for (int q = 0; q < 4; q++) accv[mt][nf][q] = 0.f;
    float dacc[2][2] = {0.f, 0.f, 0.f, 0.f};

    for (int c = 0; c < NCH; c++) {
        const int b = c & 1;
        const int jg = jbase + c * TN;

        if (c + 1 < NCH) { stage(c + 1); cp_wait<1>(); }
        else             { cp_wait<0>(); }
        __syncthreads();

        // prefetch mask fragments (fp32 LDG, hidden under QK mmas)
        float2 mlo[2], mhi[2];
#pragma unroll
        for (int mt = 0; mt < 2; mt++) {
            int rlo = row0 + wm * 32 + mt * 16 + g;
            mlo[mt] = *(const float2*)(mask + (size_t)rlo * NN + jg + wj * 8 + t * 2);
            mhi[mt] = *(const float2*)(mask + (size_t)(rlo + 8) * NN + jg + wj * 8 + t * 2);
        }

        // ---- QK^T: warp (wm,wj): rows wm*32..+31 (2 m-tiles), j-cols wj*8..+7
        float sf[2][4];
#pragma unroll
        for (int mt = 0; mt < 2; mt++)
#pragma unroll
            for (int q = 0; q < 4; q++) sf[mt][q] = 0.f;

#pragma unroll
        for (int ks = 0; ks < H; ks += 16) {
            uint32_t bb[2];
            ldsm_x2(bb[0], bb[1],
                smem_u32(&na_s[b][(wj * 8 + (lane & 7)) * 40 + ks + ((lane >> 3) & 1) * 8]));
#pragma unroll
            for (int mt = 0; mt < 2; mt++) {
                uint32_t a[4];
                ldsm_x4(a[0], a[1], a[2], a[3],
                    smem_u32(&xa_s[(wm * 32 + mt * 16 + (lane & 15)) * 40 + ks + (lane >> 4) * 8]));
                mma_bf16(sf[mt], a, bb);
            }
        }

        // ---- mask*s, exp (fp32), P -> smem bf16, denominator accum ----
#pragma unroll
        for (int mt = 0; mt < 2; mt++) {
            float p0 = __expf(sf[mt][0] * mlo[mt].x);
            float p1 = __expf(sf[mt][1] * mlo[mt].y);
            float p2 = __expf(sf[mt][2] * mhi[mt].x);
            float p3 = __expf(sf[mt][3] * mhi[mt].y);
            dacc[mt][0] += p0 + p1;
            dacc[mt][1] += p2 + p3;
            *(__nv_bfloat162*)&P_s[(wm * 32 + mt * 16 + g) * 40 + wj * 8 + t * 2] =
                __floats2bfloat162_rn(p0, p1);
            *(__nv_bfloat162*)&P_s[(wm * 32 + mt * 16 + 8 + g) * 40 + wj * 8 + t * 2] =
                __floats2bfloat162_rn(p2, p3);
        }
        __syncthreads();

        // ---- PV: acc[64 x 256] += P[64 x 32] @ V[32 x 256] ----
#pragma unroll
        for (int ks = 0; ks < TN; ks += 16) {
            uint32_t a[4][4];
#pragma unroll
            for (int mt = 0; mt < 4; mt++)
                ldsm_x4(a[mt][0], a[mt][1], a[mt][2], a[mt][3],
                    smem_u32(&P_s[(mt * 16 + (lane & 15)) * 40 + ks + (lane >> 4) * 8]));
#pragma unroll
            for (int nf = 0; nf < 4; nf++) {
                uint32_t bb[2];
                ldsm_x2t(bb[0], bb[1],
                    smem_u32(&V_s[b][(ks + (lane & 15)) * 264 + w * 32 + nf * 8]));
#pragma unroll
                for (int mt = 0; mt < 4; mt++)
                    mma_bf16(accv[mt][nf], a[mt], bb);
            }
        }
        __syncthreads();   // protect P_s / V_s before next chunk
    }

    // ---- denominators: reduce over t lanes, then across the 4 wj warps ----
    float* dsum = (float*)P_s;   // alias: P_s dead after final PV + sync
#pragma unroll
    for (int off = 1; off <= 2; off <<= 1) {
        dacc[0][0] += __shfl_xor_sync(0xffffffffu, dacc[0][0], off);
        dacc[0][1] += __shfl_xor_sync(0xffffffffu, dacc[0][1], off);
        dacc[1][0] += __shfl_xor_sync(0xffffffffu, dacc[1][0], off);
        dacc[1][1] += __shfl_xor_sync(0xffffffffu, dacc[1][1], off);
    }
    if (t == 0) {
        dsum[wj * TM2 + wm * 32 + g]      = dacc[0][0];
        dsum[wj * TM2 + wm * 32 + 8 + g]  = dacc[0][1];
        dsum[wj * TM2 + wm * 32 + 16 + g] = dacc[1][0];
        dsum[wj * TM2 + wm * 32 + 24 + g] = dacc[1][1];
    }
    __syncthreads();
    if (tid < TM2)
        g_pden[jq][row0 + tid] = dsum[tid] + dsum[TM2 + tid]
                               + dsum[2 * TM2 + tid] + dsum[3 * TM2 + tid];

    // ---- partial numerators ----
    float* np = &g_pnum[jq][0];
#pragma unroll
    for (int mt = 0; mt < 4; mt++) {
#pragma unroll
        for (int nf = 0; nf < 4; nf++) {
            int col = w * 32 + nf * 8 + t * 2;
            size_t blo = (size_t)(row0 + mt * 16 + g) * DIN + col;
            size_t bhi = (size_t)(row0 + mt * 16 + 8 + g) * DIN + col;
            *(float2*)&np[blo] = make_float2(accv[mt][nf][0], accv[mt][nf][1]);
            *(float2*)&np[bhi] = make_float2(accv[mt][nf][2], accv[mt][nf][3]);
        }
    }
}

// ---------------------------------------------------------------------------
// K3: out = sigmoid([x, agg] @ fcx_w + fcx_b); agg materialized on the fly
// from the 8 split-j partials. 128 CTAs x 16 rows, K=512.
// ---------------------------------------------------------------------------
__global__ __launch_bounds__(256) void k3_fc(
    const float* __restrict__ x, const float* __restrict__ fcw,
    const float* __restrict__ fcb, float* __restrict__ out)
{
    __shared__ float As[32][TM];      // [kk][r]
    __shared__ float Ws[32][DOUT];    // 32 KB
    __shared__ float bs[DOUT];
    __shared__ float invden[TM];

    const int tid = threadIdx.x;
    const int row0 = blockIdx.x * TM;
    bs[tid] = fcb[tid];
    if (tid < TM) {
        float d = 0.f;
#pragma unroll
        for (int p = 0; p < JSPLIT; p++) d += g_pden[p][row0 + tid];
        invden[tid] = 1.f / d;
    }

    float acc[4][4];
#pragma unroll
    for (int a = 0; a < 4; a++)
#pragma unroll
        for (int b = 0; b < 4; b++) acc[a][b] = 0.f;

    const int rg = tid >> 6, cg = tid & 63;

    for (int k0 = 0; k0 < 2 * DIN; k0 += 32) {
        for (int i = tid; i < TM * 32; i += 256) {
            int r = i & 15, kk = i >> 4;
            int k = k0 + kk;
            float v;
            if (k < DIN) {
                v = x[(size_t)(row0 + r) * DIN + k];
            } else {
                size_t idx = (size_t)(row0 + r) * DIN + (k - DIN);
                float n = 0.f;
#pragma unroll
                for (int p = 0; p < JSPLIT; p++) n += g_pnum[p][idx];
                v = 1.f / (1.f + __expf(-n * invden[r]));
            }
            As[kk][r] = v;
        }
        for (int i = tid; i < 32 * DOUT / 4; i += 256)
            ((float4*)Ws)[i] = ((const float4*)(fcw + (size_t)k0 * DOUT))[i];
        __syncthreads();

#pragma unroll 8
        for (int kk = 0; kk < 32; kk++) {
            float4 a4 = *(const float4*)&As[kk][rg * 4];
            float4 w4 = *(const float4*)&Ws[kk][cg * 4];
            acc[0][0] = fmaf(a4.x, w4.x, acc[0][0]);
            acc[0][1] = fmaf(a4.x, w4.y, acc[0][1]);
            acc[0][2] = fmaf(a4.x, w4.z, acc[0][2]);
            acc[0][3] = fmaf(a4.x, w4.w, acc[0][3]);
            acc[1][0] = fmaf(a4.y, w4.x, acc[1][0]);
            acc[1][1] = fmaf(a4.y, w4.y, acc[1][1]);
            acc[1][2] = fmaf(a4.y, w4.z, acc[1][2]);
            acc[1][3] = fmaf(a4.y, w4.w, acc[1][3]);
            acc[2][0] = fmaf(a4.z, w4.x, acc[2][0]);
            acc[2][1] = fmaf(a4.z, w4.y, acc[2][1]);
            acc[2][2] = fmaf(a4.z, w4.z, acc[2][2]);
            acc[2][3] = fmaf(a4.z, w4.w, acc[2][3]);
            acc[3][0] = fmaf(a4.w, w4.x, acc[3][0]);
            acc[3][1] = fmaf(a4.w, w4.y, acc[3][1]);
            acc[3][2] = fmaf(a4.w, w4.z, acc[3][2]);
            acc[3][3] = fmaf(a4.w, w4.w, acc[3][3]);
        }
        __syncthreads();
    }

#pragma unroll
    for (int a = 0; a < 4; a++) {
        int r = row0 + rg * 4 + a;
        float4 o;
        o.x = 1.f / (1.f + __expf(-(acc[a][0] + bs[cg * 4 + 0])));
        o.y = 1.f / (1.f + __expf(-(acc[a][1] + bs[cg * 4 + 1])));
        o.z = 1.f / (1.f + __expf(-(acc[a][2] + bs[cg * 4 + 2])));
        o.w = 1.f / (1.f + __expf(-(acc[a][3] + bs[cg * 4 + 3])));
        *(float4*)&out[(size_t)r * DOUT + cg * 4] = o;
    }
}

// ---------------------------------------------------------------------------
extern "C" void kernel_launch(void* const* d_in, const int* in_sizes, int n_in,
                              void* d_out, int out_size) {
    const float* x     = (const float*)d_in[0];
    const float* neibs = (const float*)d_in[1];
    // d_in[2] edge_emb: dead code in reference, never read
    const float* mask  = (const float*)d_in[3];
    const float* axw1  = (const float*)d_in[4];
    const float* axb1  = (const float*)d_in[5];
    const float* axw2  = (const float*)d_in[6];
    const float* axb2  = (const float*)d_in[7];
    const float* anw1  = (const float*)d_in[8];
    const float* anb1  = (const float*)d_in[9];
    const float* anw2  = (const float*)d_in[10];
    const float* anb2  = (const float*)d_in[11];
    // d_in[12..15] ae_*: dead code
    const float* fcw   = (const float*)d_in[16];
    const float* fcb   = (const float*)d_in[17];
    float* out = (float*)d_out;

    k1_att<<<256, 256>>>(x, neibs, axw1, axb1, axw2, axb2,
                         anw1, anb1, anw2, anb2);
    k2_attn<<<(NROWS / TM2) * JSPLIT, 256>>>(mask);
    k3_fc<<<NROWS / TM, 256>>>(x, fcw, fcb, out);
}

// round 17
// speedup vs baseline: 4.1376x; 1.0654x over previous
#include <cuda_runtime.h>
#include <cuda_bf16.h>
#include <cstdint>

#define NROWS 2048
#define NN    2048
#define DIN   256
#define H     32
#define DOUT  256
#define TM    16      // k3 row tile
#define TM2   64      // k2 row tile
#define TN    32      // k2 neighbor chunk
#define JSPLIT 8
#define JCH   (NN / JSPLIT)   // 256 neighbors per CTA
#define NCH   (JCH / TN)      // 8 chunks per CTA

// Scratch (no allocations allowed)
__device__ __align__(16) __nv_bfloat16 g_xa16[NROWS * H];
__device__ __align__(16) __nv_bfloat16 g_na16[NN * H];
__device__ __align__(16) __nv_bfloat16 g_nb16[NN * DIN];     // neibs in bf16
__device__ float g_pnum[JSPLIT][NROWS * DIN];                // partial numerators
__device__ float g_pden[JSPLIT][NROWS];                      // partial denominators

// ---------------------------------------------------------------------------
// helpers
// ---------------------------------------------------------------------------
__device__ __forceinline__ uint32_t smem_u32(const void* p) {
    return (uint32_t)__cvta_generic_to_shared(p);
}
__device__ __forceinline__ void ldsm_x4(uint32_t& r0, uint32_t& r1,
                                        uint32_t& r2, uint32_t& r3, uint32_t a) {
    asm volatile("ldmatrix.sync.aligned.m8n8.x4.shared.b16 {%0,%1,%2,%3}, [%4];\n"
                 : "=r"(r0), "=r"(r1), "=r"(r2), "=r"(r3) : "r"(a));
}
__device__ __forceinline__ void ldsm_x2(uint32_t& r0, uint32_t& r1, uint32_t a) {
    asm volatile("ldmatrix.sync.aligned.m8n8.x2.shared.b16 {%0,%1}, [%2];\n"
                 : "=r"(r0), "=r"(r1) : "r"(a));
}
__device__ __forceinline__ void ldsm_x2t(uint32_t& r0, uint32_t& r1, uint32_t a) {
    asm volatile("ldmatrix.sync.aligned.m8n8.x2.trans.shared.b16 {%0,%1}, [%2];\n"
                 : "=r"(r0), "=r"(r1) : "r"(a));
}
__device__ __forceinline__ void mma_bf16(float* c, const uint32_t* a, const uint32_t* b) {
    asm volatile(
        "mma.sync.aligned.m16n8k16.row.col.f32.bf16.bf16.f32 "
        "{%0,%1,%2,%3}, {%4,%5,%6,%7}, {%8,%9}, {%0,%1,%2,%3};\n"
        : "+f"(c[0]), "+f"(c[1]), "+f"(c[2]), "+f"(c[3])
        : "r"(a[0]), "r"(a[1]), "r"(a[2]), "r"(a[3]), "r"(b[0]), "r"(b[1]));
}
__device__ __forceinline__ void mma_tf32(float* c, const uint32_t* a, const uint32_t* b) {
    asm volatile(
        "mma.sync.aligned.m16n8k8.row.col.f32.tf32.tf32.f32 "
        "{%0,%1,%2,%3}, {%4,%5,%6,%7}, {%8,%9}, {%0,%1,%2,%3};\n"
        : "+f"(c[0]), "+f"(c[1]), "+f"(c[2]), "+f"(c[3])
        : "r"(a[0]), "r"(a[1]), "r"(a[2]), "r"(a[3]), "r"(b[0]), "r"(b[1]));
}
__device__ __forceinline__ uint32_t f2tf32(float v) {
    uint32_t r;
    asm("cvt.rna.tf32.f32 %0, %1;\n" : "=r"(r) : "f"(v));
    return r;
}
__device__ __forceinline__ void cp16(uint32_t dst, const void* src) {
    asm volatile("cp.async.cg.shared.global [%0], [%1], 16;\n" :: "r"(dst), "l"(src));
}
__device__ __forceinline__ void cp_commit() {
    asm volatile("cp.async.commit_group;\n");
}
template <int N>
__device__ __forceinline__ void cp_wait() {
    asm volatile("cp.async.wait_group %0;\n" :: "n"(N));
}

// ---------------------------------------------------------------------------
// K1: att = tanh(x@W1+b1)@W2+b2 for x (ax_*) and neibs (an_*), outputs bf16.
// (unchanged from R15)
// ---------------------------------------------------------------------------
__global__ __launch_bounds__(256) void k1_att(
    const float* __restrict__ x, const float* __restrict__ neibs,
    const float* __restrict__ axw1, const float* __restrict__ axb1,
    const float* __restrict__ axw2, const float* __restrict__ axb2,
    const float* __restrict__ anw1, const float* __restrict__ anb1,
    const float* __restrict__ anw2, const float* __restrict__ anb2)
{
    __shared__ float W1s[DIN * H];       // 32 KB
    __shared__ float rows_s[16 * DIN];   // 16 KB

    const int tid = threadIdx.x;
    const int cta = blockIdx.x;
    const bool isx = (cta < 128);
    const float* W1 = isx ? axw1 : anw1;
    const float* W2 = isx ? axw2 : anw2;
    const float* B1 = isx ? axb1 : anb1;
    const float* B2 = isx ? axb2 : anb2;
    const float* src = isx ? x : neibs;
    __nv_bfloat16* dst = isx ? g_xa16 : g_na16;
    const int row0 = (cta & 127) * 16;
    const int w = tid >> 5, l = tid & 31;

#pragma unroll
    for (int i = 0; i < 4; i++) {
        int idx = tid + i * 256;
        cp16(smem_u32(&rows_s[idx * 4]),
             src + (size_t)row0 * DIN + idx * 4);
    }
    cp_commit();

    for (int i = tid; i < DIN * H / 4; i += 256)
        ((float4*)W1s)[i] = ((const float4*)W1)[i];

    float wreg[H];
#pragma unroll
    for (int m = 0; m < H; m++) wreg[m] = W2[m * H + l];
    float b1v = B1[l], b2v = B2[l];

    cp_wait<0>();
    __syncthreads();

    if (!isx) {
        __nv_bfloat162* nb2p = (__nv_bfloat162*)g_nb16 + (size_t)row0 * DIN / 2;
        for (int i = tid; i < 16 * DIN / 2; i += 256) {
            float2 v = *(const float2*)&rows_s[i * 2];
            nb2p[i] = __floats2bfloat162_rn(v.x, v.y);
        }
    }

    const float* r0p = &rows_s[(w * 2 + 0) * DIN];
    const float* r1p = &rows_s[(w * 2 + 1) * DIN];

    float h1a0 = b1v, h1b0 = 0.f, h1a1 = b1v, h1b1 = 0.f;
#pragma unroll 8
    for (int k = 0; k < DIN; k += 4) {
        float4 x0 = *(const float4*)(r0p + k);
        float4 x1 = *(const float4*)(r1p + k);
        float w0 = W1s[(k + 0) * H + l];
        float w1 = W1s[(k + 1) * H + l];
        float w2 = W1s[(k + 2) * H + l];
        float w3 = W1s[(k + 3) * H + l];
        h1a0 = fmaf(x0.x, w0, h1a0); h1b0 = fmaf(x0.z, w2, h1b0);
        h1a0 = fmaf(x0.y, w1, h1a0); h1b0 = fmaf(x0.w, w3, h1b0);
        h1a1 = fmaf(x1.x, w0, h1a1); h1b1 = fmaf(x1.z, w2, h1b1);
        h1a1 = fmaf(x1.y, w1, h1a1); h1b1 = fmaf(x1.w, w3, h1b1);
    }
    float h1_0 = tanhf(h1a0 + h1b0);
    float h1_1 = tanhf(h1a1 + h1b1);

    float h2_0 = b2v, h2_1 = b2v;
#pragma unroll
    for (int m = 0; m < H; m++) {
        h2_0 = fmaf(__shfl_sync(0xffffffffu, h1_0, m), wreg[m], h2_0);
        h2_1 = fmaf(__shfl_sync(0xffffffffu, h1_1, m), wreg[m], h2_1);
    }
    dst[(size_t)(row0 + w * 2 + 0) * H + l] = __float2bfloat16(h2_0);
    dst[(size_t)(row0 + w * 2 + 1) * H + l] = __float2bfloat16(h2_1);
}

// ---------------------------------------------------------------------------
// K2: fused masked-softmax attention, tensor cores, cp.async double-buffered.
// (unchanged from R15)
// ---------------------------------------------------------------------------
__global__ __launch_bounds__(256) void k2_attn(const float* __restrict__ mask)
{
    __shared__ __align__(16) __nv_bfloat16 xa_s[TM2 * 40];
    __shared__ __align__(16) __nv_bfloat16 na_s[2][TN * 40];
    __shared__ __align__(16) __nv_bfloat16 V_s[2][TN * 264];
    __shared__ __align__(16) __nv_bfloat16 P_s[TM2 * 40];

    const int tid = threadIdx.x;
    const int w = tid >> 5, lane = tid & 31;
    const int g = lane >> 2, t = lane & 3;
    const int wj = w & 3, wm = w >> 2;
    const int tile = blockIdx.x >> 3;
    const int jq   = blockIdx.x & 7;
    const int row0 = tile * TM2;
    const int jbase = jq * JCH;

    auto stage = [&](int c) {
        int b = c & 1;
        int jg = jbase + c * TN;
        if (tid < 128) {
            int r = tid >> 2, q = tid & 3;
            cp16(smem_u32(&na_s[b][r * 40 + q * 8]),
                 &g_na16[(size_t)(jg + r) * H + q * 8]);
        }
#pragma unroll
        for (int i = 0; i < 4; i++) {
            int idx = tid + i * 256;
            int r = idx >> 5, q = idx & 31;
            cp16(smem_u32(&V_s[b][r * 264 + q * 8]),
                 &g_nb16[(size_t)(jg + r) * DIN + q * 8]);
        }
        cp_commit();
    };

    {
        int r = tid >> 2, q = tid & 3;
        cp16(smem_u32(&xa_s[r * 40 + q * 8]),
             &g_xa16[(size_t)(row0 + r) * H + q * 8]);
    }
    stage(0);

    float accv[4][4][4];
#pragma unroll
    for (int mt = 0; mt < 4; mt++)
#pragma unroll
        for (int nf = 0; nf < 4; nf++)
#pragma unroll
            for (int q = 0; q < 4; q++) accv[mt][nf][q] = 0.f;
    float dacc[2][2] = {0.f, 0.f, 0.f, 0.f};

    for (int c = 0; c < NCH; c++) {
        const int b = c & 1;
        const int jg = jbase + c * TN;

        if (c + 1 < NCH) { stage(c + 1); cp_wait<1>(); }
        else             { cp_wait<0>(); }
        __syncthreads();

        float2 mlo[2], mhi[2];
#pragma unroll
        for (int mt = 0; mt < 2; mt++) {
            int rlo = row0 + wm * 32 + mt * 16 + g;
            mlo[mt] = *(const float2*)(mask + (size_t)rlo * NN + jg + wj * 8 + t * 2);
            mhi[mt] = *(const float2*)(mask + (size_t)(rlo + 8) * NN + jg + wj * 8 + t * 2);
        }

        float sf[2][4];
#pragma unroll
        for (int mt = 0; mt < 2; mt++)
#pragma unroll
            for (int q = 0; q < 4; q++) sf[mt][q] = 0.f;

#pragma unroll
        for (int ks = 0; ks < H; ks += 16) {
            uint32_t bb[2];
            ldsm_x2(bb[0], bb[1],
                smem_u32(&na_s[b][(wj * 8 + (lane & 7)) * 40 + ks + ((lane >> 3) & 1) * 8]));
#pragma unroll
            for (int mt = 0; mt < 2; mt++) {
                uint32_t a[4];
                ldsm_x4(a[0], a[1], a[2], a[3],
                    smem_u32(&xa_s[(wm * 32 + mt * 16 + (lane & 15)) * 40 + ks + (lane >> 4) * 8]));
                mma_bf16(sf[mt], a, bb);
            }
        }

#pragma unroll
        for (int mt = 0; mt < 2; mt++) {
            float p0 = __expf(sf[mt][0] * mlo[mt].x);
            float p1 = __expf(sf[mt][1] * mlo[mt].y);
            float p2 = __expf(sf[mt][2] * mhi[mt].x);
            float p3 = __expf(sf[mt][3] * mhi[mt].y);
            dacc[mt][0] += p0 + p1;
            dacc[mt][1] += p2 + p3;
            *(__nv_bfloat162*)&P_s[(wm * 32 + mt * 16 + g) * 40 + wj * 8 + t * 2] =
                __floats2bfloat162_rn(p0, p1);
            *(__nv_bfloat162*)&P_s[(wm * 32 + mt * 16 + 8 + g) * 40 + wj * 8 + t * 2] =
                __floats2bfloat162_rn(p2, p3);
        }
        __syncthreads();

#pragma unroll
        for (int ks = 0; ks < TN; ks += 16) {
            uint32_t a[4][4];
#pragma unroll
            for (int mt = 0; mt < 4; mt++)
                ldsm_x4(a[mt][0], a[mt][1], a[mt][2], a[mt][3],
                    smem_u32(&P_s[(mt * 16 + (lane & 15)) * 40 + ks + (lane >> 4) * 8]));
#pragma unroll
            for (int nf = 0; nf < 4; nf++) {
                uint32_t bb[2];
                ldsm_x2t(bb[0], bb[1],
                    smem_u32(&V_s[b][(ks + (lane & 15)) * 264 + w * 32 + nf * 8]));
#pragma unroll
                for (int mt = 0; mt < 4; mt++)
                    mma_bf16(accv[mt][nf], a[mt], bb);
            }
        }
        __syncthreads();
    }

    float* dsum = (float*)P_s;
#pragma unroll
    for (int off = 1; off <= 2; off <<= 1) {
        dacc[0][0] += __shfl_xor_sync(0xffffffffu, dacc[0][0], off);
        dacc[0][1] += __shfl_xor_sync(0xffffffffu, dacc[0][1], off);
        dacc[1][0] += __shfl_xor_sync(0xffffffffu, dacc[1][0], off);
        dacc[1][1] += __shfl_xor_sync(0xffffffffu, dacc[1][1], off);
    }
    if (t == 0) {
        dsum[wj * TM2 + wm * 32 + g]      = dacc[0][0];
        dsum[wj * TM2 + wm * 32 + 8 + g]  = dacc[0][1];
        dsum[wj * TM2 + wm * 32 + 16 + g] = dacc[1][0];
        dsum[wj * TM2 + wm * 32 + 24 + g] = dacc[1][1];
    }
    __syncthreads();
    if (tid < TM2)
        g_pden[jq][row0 + tid] = dsum[tid] + dsum[TM2 + tid]
                               + dsum[2 * TM2 + tid] + dsum[3 * TM2 + tid];

    float* np = &g_pnum[jq][0];
#pragma unroll
    for (int mt = 0; mt < 4; mt++) {
#pragma unroll
        for (int nf = 0; nf < 4; nf++) {
            int col = w * 32 + nf * 8 + t * 2;
            size_t blo = (size_t)(row0 + mt * 16 + g) * DIN + col;
            size_t bhi = (size_t)(row0 + mt * 16 + 8 + g) * DIN + col;
            *(float2*)&np[blo] = make_float2(accv[mt][nf][0], accv[mt][nf][1]);
            *(float2*)&np[bhi] = make_float2(accv[mt][nf][2], accv[mt][nf][3]);
        }
    }
}

// ---------------------------------------------------------------------------
// K3: out = sigmoid([x, agg] @ fcx_w + fcx_b) on tf32 TENSOR CORES.
// Same staging as before (A combine+sigmoid in fp32, W fp32 -> smem), but the
// inner product runs mma.m16n8k8.tf32 (cvt.rna inputs) instead of FFMA —
// the fp32 FFMA pipe was the proven roofline here. Ws stride 264 makes the
// B-fragment LDS (t -> +8 banks) conflict-free. 128 CTAs x 16 rows.
// Warp w owns cols w*32..w*32+31 (4 n-tiles of 8).
// ---------------------------------------------------------------------------
__global__ __launch_bounds__(256) void k3_fc(
    const float* __restrict__ x, const float* __restrict__ fcw,
    const float* __restrict__ fcb, float* __restrict__ out)
{
    __shared__ float As[32][TM];       // [kk][r], 2 KB
    __shared__ float Ws[32][264];      // [kk][col], padded, 33 KB
    __shared__ float bs[DOUT];
    __shared__ float invden[TM];

    const int tid = threadIdx.x;
    const int w = tid >> 5, lane = tid & 31;
    const int g = lane >> 2, t = lane & 3;
    const int row0 = blockIdx.x * TM;
    bs[tid] = fcb[tid];
    if (tid < TM) {
        float d = 0.f;
#pragma unroll
        for (int p = 0; p < JSPLIT; p++) d += g_pden[p][row0 + tid];
        invden[tid] = 1.f / d;
    }

    float acc[4][4];
#pragma unroll
    for (int nt = 0; nt < 4; nt++)
#pragma unroll
        for (int q = 0; q < 4; q++) acc[nt][q] = 0.f;

    for (int k0 = 0; k0 < 2 * DIN; k0 += 32) {
        // ---- stage A tile (combine partials + sigmoid for agg half) ----
        for (int i = tid; i < TM * 32; i += 256) {
            int r = i & 15, kk = i >> 4;
            int k = k0 + kk;
            float v;
            if (k < DIN) {
                v = x[(size_t)(row0 + r) * DIN + k];
            } else {
                size_t idx = (size_t)(row0 + r) * DIN + (k - DIN);
                float n = 0.f;
#pragma unroll
                for (int p = 0; p < JSPLIT; p++) n += g_pnum[p][idx];
                v = 1.f / (1.f + __expf(-n * invden[r]));
            }
            As[kk][r] = v;
        }
        // ---- stage W tile (fp32, padded stride) ----
        for (int i = tid; i < 32 * DOUT / 4; i += 256) {
            int r = i >> 6, c4 = (i & 63) * 4;
            *(float4*)&Ws[r][c4] = ((const float4*)(fcw + (size_t)(k0 + r) * DOUT))[i & 63];
        }
        __syncthreads();

        // ---- tf32 mma: 4 k8-steps x 4 n-tiles ----
#pragma unroll
        for (int ks = 0; ks < 32; ks += 8) {
            uint32_t a[4];
            a[0] = f2tf32(As[ks + t][g]);
            a[1] = f2tf32(As[ks + t][g + 8]);
            a[2] = f2tf32(As[ks + t + 4][g]);
            a[3] = f2tf32(As[ks + t + 4][g + 8]);
#pragma unroll
            for (int nt = 0; nt < 4; nt++) {
                int col = w * 32 + nt * 8 + g;
                uint32_t b[2];
                b[0] = f2tf32(Ws[ks + t][col]);
                b[1] = f2tf32(Ws[ks + t + 4][col]);
                mma_tf32(acc[nt], a, b);
            }
        }
        __syncthreads();
    }

    // ---- epilogue: bias + sigmoid; thread holds rows g/g+8, cols 2t,2t+1 ----
#pragma unroll
    for (int nt = 0; nt < 4; nt++) {
        int col = w * 32 + nt * 8 + t * 2;
        float b0 = bs[col], b1 = bs[col + 1];
        float2 olo, ohi;
        olo.x = 1.f / (1.f + __expf(-(acc[nt][0] + b0)));
        olo.y = 1.f / (1.f + __expf(-(acc[nt][1] + b1)));
        ohi.x = 1.f / (1.f + __expf(-(acc[nt][2] + b0)));
        ohi.y = 1.f / (1.f + __expf(-(acc[nt][3] + b1)));
        *(float2*)&out[(size_t)(row0 + g) * DOUT + col] = olo;
        *(float2*)&out[(size_t)(row0 + 8 + g) * DOUT + col] = ohi;
    }
}

// ---------------------------------------------------------------------------
extern "C" void kernel_launch(void* const* d_in, const int* in_sizes, int n_in,
                              void* d_out, int out_size) {
    const float* x     = (const float*)d_in[0];
    const float* neibs = (const float*)d_in[1];
    // d_in[2] edge_emb: dead code in reference, never read
    const float* mask  = (const float*)d_in[3];
    const float* axw1  = (const float*)d_in[4];
    const float* axb1  = (const float*)d_in[5];
    const float* axw2  = (const float*)d_in[6];
    const float* axb2  = (const float*)d_in[7];
    const float* anw1  = (const float*)d_in[8];
    const float* anb1  = (const float*)d_in[9];
    const float* anw2  = (const float*)d_in[10];
    const float* anb2  = (const float*)d_in[11];
    // d_in[12..15] ae_*: dead code
    const float* fcw   = (const float*)d_in[16];
    const float* fcb   = (const float*)d_in[17];
    float* out = (float*)d_out;

    k1_att<<<256, 256>>>(x, neibs, axw1, axb1, axw2, axb2,
                         anw1, anb1, anw2, anb2);
    k2_attn<<<(NROWS / TM2) * JSPLIT, 256>>>(mask);
    k3_fc<<<NROWS / TM, 256>>>(x, fcw, fcb, out);
}